// round 9
// baseline (speedup 1.0000x reference)
#include <cuda_runtime.h>
#include <cuda_fp16.h>
#include <cstdint>

// ---------------- problem constants ----------------
#define BB    4
#define NQ    384
#define NK    384
#define DE    64
#define DMSG  64
#define DFF   256
#define DOUT  64
#define DINV  256

#define TQ    16
#define TK    8
#define TM    128          // pairs per tile

#define LDA   136          // half pitch for sA (k=128 + 8 pad)
#define LDAQ  260          // float pitch for sAq/sAk

#define NPRE  (BB * (NQ + NK))   // 3072 prelude blocks
#define NPREP 96                 // weight-prep blocks (96*256 = 24576 = exactly one u32 each)

// ---------------- device scratch ----------------
__device__ float g_Aq[BB * NQ * DFF];
__device__ float g_Ak[BB * NK * DFF];
// Fragment-major weight images: one uint4 (16B) per lane per 16n x 16k mma tile.
// W1F: [c:4][kk:8][jp:4][lane:32] uint4   (GEMM1: W1 rows 128..255 transposed)
// W2F: [c:4][kk:4][jp:4][lane:32] uint4   (GEMM2: W2 transposed)
__device__ __align__(16) uint32_t g_W1F[4 * 8 * 4 * 32 * 4];   // 65536 B
__device__ __align__(16) uint32_t g_W2F[4 * 4 * 4 * 32 * 4];   // 32768 B

// ---------------- SMEM map (bytes) ----------------
#define OFF_SA   0        // 128*136*2 = 34816
#define OFF_AQ   34816    // 16*260*4  = 16640
#define OFF_AK   51456    //  8*260*4  =  8320
#define OFF_EQ   59776    // equi staging: 24*192*4 = 18432
#define OFF_B2   78208    // 256
#define SMEM_BYTES 78464

__device__ __forceinline__ uint32_t smem_u32(const void* p) {
    uint32_t a;
    asm("{ .reg .u64 t; cvta.to.shared.u64 t, %1; cvt.u32.u64 %0, t; }" : "=r"(a) : "l"(p));
    return a;
}
#define CP_ASYNC16(dst, src) \
    asm volatile("cp.async.cg.shared.global [%0], [%1], 16;" :: "r"(dst), "l"(src))
#define CP_COMMIT() asm volatile("cp.async.commit_group;" ::: "memory")
#define CP_WAIT(n)  asm volatile("cp.async.wait_group %0;" :: "n"(n) : "memory")

__device__ __forceinline__ void ldsm4(uint32_t& r0, uint32_t& r1, uint32_t& r2, uint32_t& r3,
                                      uint32_t addr) {
    asm volatile("ldmatrix.sync.aligned.m8n8.x4.shared.b16 {%0,%1,%2,%3}, [%4];"
        : "=r"(r0), "=r"(r1), "=r"(r2), "=r"(r3) : "r"(addr));
}
__device__ __forceinline__ void mma16816(float* c, uint32_t a0, uint32_t a1, uint32_t a2,
                                         uint32_t a3, uint32_t b0, uint32_t b1) {
    asm volatile(
        "mma.sync.aligned.m16n8k16.row.col.f32.f16.f16.f32 "
        "{%0,%1,%2,%3}, {%4,%5,%6,%7}, {%8,%9}, {%0,%1,%2,%3};"
        : "+f"(c[0]), "+f"(c[1]), "+f"(c[2]), "+f"(c[3])
        : "r"(a0), "r"(a1), "r"(a2), "r"(a3), "r"(b0), "r"(b1));
}
// silu on a half2: h = 0.5x + 0.5x * tanh(0.5x)
__device__ __forceinline__ uint32_t silu_h2(uint32_t xu) {
    uint32_t hxu, tu, res;
    asm("mul.rn.f16x2 %0, %1, %2;" : "=r"(hxu) : "r"(xu), "r"(0x38003800u));
    asm("tanh.approx.f16x2 %0, %1;" : "=r"(tu) : "r"(hxu));
    asm("fma.rn.f16x2 %0, %1, %2, %3;" : "=r"(res) : "r"(hxu), "r"(tu), "r"(hxu));
    return res;
}

// ---------------- prelude: A_q / A_k (+ appended fragment-prep) ----------------
__global__ void __launch_bounds__(256) prelude_kernel(
    const float* __restrict__ q_inv, const float* __restrict__ k_inv,
    const float* __restrict__ Wq, const float* __restrict__ bq,
    const float* __restrict__ Wk, const float* __restrict__ bk,
    const float* __restrict__ W1, const float* __restrict__ b1,
    const float* __restrict__ W2)
{
    int blk = blockIdx.x;

    if (blk >= NPRE) {
        // One u32 fragment word per thread. B-frag image for mma.m16n8k16:
        // u32 i of lane L in tile (n0,k0):  n = n0 + ((i>>1)&1)*8 + (L>>2)
        //                                   k = k0 + (i&1)*8 + (L&3)*2   (half2: {k, k+1})
        int idx = (blk - NPRE) * 256 + threadIdx.x;          // 0 .. 24575
        if (idx < 16384) {                                   // W1F
            int i    = idx & 3;
            int lane = (idx >> 2) & 31;
            int jp   = (idx >> 7) & 3;
            int kk   = (idx >> 9) & 7;
            int c    = idx >> 12;
            int n = c * 64 + jp * 16 + ((i >> 1) & 1) * 8 + (lane >> 2);
            int k = kk * 16 + (i & 1) * 8 + (lane & 3) * 2;  // 0..126
            __half2 v = __floats2half2_rn(W1[(128 + k) * DFF + n],
                                          W1[(128 + k + 1) * DFF + n]);
            g_W1F[idx] = *(uint32_t*)&v;
        } else {                                             // W2F
            int j    = idx - 16384;
            int i    = j & 3;
            int lane = (j >> 2) & 31;
            int jp   = (j >> 7) & 3;
            int kk   = (j >> 9) & 3;
            int c    = j >> 11;
            int n = jp * 16 + ((i >> 1) & 1) * 8 + (lane >> 2);
            int k = c * 64 + kk * 16 + (i & 1) * 8 + (lane & 3) * 2;  // 0..254
            __half2 v = __floats2half2_rn(W2[k * DOUT + n],
                                          W2[(k + 1) * DOUT + n]);
            g_W2F[j] = *(uint32_t*)&v;
        }
        return;
    }

    bool isQ = blk < BB * NQ;
    int bn = isQ ? blk : blk - BB * NQ;

    const float* inv  = isQ ? (q_inv + bn * DINV) : (k_inv + bn * DINV);
    const float* W    = isQ ? Wq : Wk;
    const float* bias = isQ ? bq : bk;
    const float* W1s  = isQ ? W1 : (W1 + DMSG * DFF);
    float* A          = isQ ? (g_Aq + bn * DFF) : (g_Ak + bn * DFF);

    __shared__ float s_inv[DINV];
    __shared__ float s_part[4][DMSG];
    __shared__ float s_msg[DMSG];

    int tid = threadIdx.x;
    s_inv[tid] = inv[tid];
    __syncthreads();

    int m = tid & 63, g = tid >> 6;
    float acc = 0.f;
    #pragma unroll 16
    for (int i = g * 64; i < g * 64 + 64; i++)
        acc = fmaf(s_inv[i], W[i * DMSG + m], acc);
    s_part[g][m] = acc;
    __syncthreads();
    if (tid < DMSG)
        s_msg[tid] = s_part[0][tid] + s_part[1][tid] + s_part[2][tid] + s_part[3][tid] + bias[tid];
    __syncthreads();

    float a = isQ ? b1[tid] : 0.f;
    #pragma unroll 32
    for (int mm = 0; mm < DMSG; mm++)
        a = fmaf(s_msg[mm], W1s[mm * DFF + tid], a);
    A[tid] = a;
}

// ---------------- main pairwise kernel (2 CTAs/SM, barrier-free mainloop) ----------------
__global__ void __launch_bounds__(256, 2) pair_kernel(
    const float* __restrict__ q_equi, const float* __restrict__ k_equi,
    const float* __restrict__ b2, float* __restrict__ out)
{
    extern __shared__ char smem[];
    const uint32_t sb = smem_u32(smem);
    int tid = threadIdx.x;
    int w = tid >> 5, lane = tid & 31;

    int b  = blockIdx.z;
    int q0 = blockIdx.y * TQ;
    int k0 = blockIdx.x * TK;

    __half* sA  = (__half*)(smem + OFF_SA);
    float*  sAq = (float*)(smem + OFF_AQ);
    float*  sAk = (float*)(smem + OFF_AK);
    float*  sb2 = (float*)(smem + OFF_B2);

    // ---- phase 0: async-stage equi, Aq/Ak, b2 ----
    {
        const uint32_t sqe_b = sb + OFF_EQ;
        const uint32_t ske_b = sqe_b + TQ * 192 * 4;
        const char* qsrc = (const char*)(q_equi + (size_t)(b * NQ + q0) * 192);
        const char* ksrc = (const char*)(k_equi + (size_t)(b * NK + k0) * 192);
        #pragma unroll
        for (int i = tid; i < 768; i += 256) CP_ASYNC16(sqe_b + i * 16, qsrc + i * 16);
        #pragma unroll
        for (int i = tid; i < 384; i += 256) CP_ASYNC16(ske_b + i * 16, ksrc + i * 16);
        const char* aqsrc = (const char*)(g_Aq + (size_t)(b * NQ + q0) * DFF);
        const char* aksrc = (const char*)(g_Ak + (size_t)(b * NK + k0) * DFF);
        #pragma unroll
        for (int i = tid; i < 1024; i += 256) {
            int row = i >> 6, c4 = i & 63;
            CP_ASYNC16(sb + OFF_AQ + (row * LDAQ + c4 * 4) * 4, aqsrc + i * 16);
        }
        #pragma unroll
        for (int i = tid; i < 512; i += 256) {
            int row = i >> 6, c4 = i & 63;
            CP_ASYNC16(sb + OFF_AK + (row * LDAQ + c4 * 4) * 4, aksrc + i * 16);
        }
        if (tid < 16) CP_ASYNC16(sb + OFF_B2 + tid * 16, (const char*)b2 + tid * 16);
        CP_COMMIT();
        CP_WAIT(0);
        __syncthreads();
    }

    // ---- phase 1: dot & dist -> sA fp16 [128][LDA] ----
    {
        const float* sqe = (const float*)(smem + OFF_EQ);
        const float* ske = sqe + TQ * 192;
        int p0 = tid >> 5, e2 = (tid & 31) * 2;
        const float* kr = ske + p0 * 192 + e2;
        float2 g0 = *(const float2*)(kr);
        float2 g1 = *(const float2*)(kr + 64);
        float2 g2 = *(const float2*)(kr + 128);
        #pragma unroll
        for (int n = 0; n < 16; n++) {
            int p = n * 8 + p0;                 // qi = n, ki = p0
            const float* qr = sqe + n * 192 + e2;
            float2 a0 = *(const float2*)(qr);
            float2 a1 = *(const float2*)(qr + 64);
            float2 a2 = *(const float2*)(qr + 128);
            float dx = a0.x * g0.x + a1.x * g1.x + a2.x * g2.x;
            float dy = a0.y * g0.y + a1.y * g1.y + a2.y * g2.y;
            float fx0 = a0.x - g0.x, fx1 = a1.x - g1.x, fx2 = a2.x - g2.x;
            float fy0 = a0.y - g0.y, fy1 = a1.y - g1.y, fy2 = a2.y - g2.y;
            float sx = sqrtf(fx0 * fx0 + fx1 * fx1 + fx2 * fx2);
            float sy = sqrtf(fy0 * fy0 + fy1 * fy1 + fy2 * fy2);
            *(__half2*)(sA + p * LDA + e2)      = __floats2half2_rn(dx, dy);
            *(__half2*)(sA + p * LDA + 64 + e2) = __floats2half2_rn(sx, sy);
        }
    }
    __syncthreads();   // sA / sAq / sAk read-only from here: no more block barriers

    // ---- lane geometry ----
    const int m0 = w * 16;
    const uint32_t aAddr1 = sb + OFF_SA + ((m0 + (lane & 15)) * LDA + (lane >> 4) * 8) * 2;
    const int r = lane >> 2, cp = (lane & 3) * 2;
    const int m_lo = m0 + r;
    const int qi_lo = m_lo >> 3, ki = m_lo & 7;   // ki_hi == ki_lo; qi_hi = qi_lo + 1

    // ---- hoisted GEMM1 A-fragments (chunk-invariant) ----
    uint32_t af[8][4];
    #pragma unroll
    for (int kk = 0; kk < 8; kk++)
        ldsm4(af[kk][0], af[kk][1], af[kk][2], af[kk][3], aAddr1 + kk * 32);

    float acc2[8][4];
    #pragma unroll
    for (int j = 0; j < 8; j++)
        #pragma unroll
        for (int i = 0; i < 4; i++) acc2[j][i] = 0.f;

    const uint4* w1f = (const uint4*)g_W1F + lane;   // + ((c*8+kk)*4+jp)*32
    const uint4* w2f = (const uint4*)g_W2F + lane;   // + ((c*4+kk)*4+jp)*32

    // ================= chunk loop over N (4 x 64): barrier-free =================
    for (int c = 0; c < 4; c++) {
        // ---- GEMM1 chunk: acc1[16,64] = A[16,128] @ W1c^T (B direct from global) ----
        float acc1[8][4];
        #pragma unroll
        for (int j = 0; j < 8; j++)
            #pragma unroll
            for (int i = 0; i < 4; i++) acc1[j][i] = 0.f;

        const uint4* w1c = w1f + c * 1024;
        #pragma unroll
        for (int kk = 0; kk < 8; kk++) {
            #pragma unroll
            for (int jp = 0; jp < 4; jp++) {
                uint4 f = __ldg(w1c + (kk * 4 + jp) * 32);
                mma16816(acc1[2 * jp],     af[kk][0], af[kk][1], af[kk][2], af[kk][3], f.x, f.y);
                mma16816(acc1[2 * jp + 1], af[kk][0], af[kk][1], af[kk][2], af[kk][3], f.z, f.w);
            }
        }

        // ---- epilogue1: + Aq + Ak (ak shared lo/hi), SiLU -> register h fragments ----
        uint32_t hlo[8], hhi[8];
        {
            const float* aqlo = sAq + qi_lo * LDAQ + c * 64;
            const float* aqhi = aqlo + LDAQ;                 // qi_hi = qi_lo + 1
            const float* akr  = sAk + ki * LDAQ + c * 64;    // same row for lo & hi
            #pragma unroll
            for (int j = 0; j < 8; j++) {
                int n = j * 8 + cp;
                float2 aql = *(const float2*)(aqlo + n);
                float2 aqh = *(const float2*)(aqhi + n);
                float2 akl = *(const float2*)(akr + n);
                float v0 = acc1[j][0] + aql.x + akl.x;
                float v1 = acc1[j][1] + aql.y + akl.y;
                float v2 = acc1[j][2] + aqh.x + akl.x;
                float v3 = acc1[j][3] + aqh.y + akl.y;
                __half2 x0 = __floats2half2_rn(v0, v1);
                __half2 x1 = __floats2half2_rn(v2, v3);
                hlo[j] = silu_h2(*(uint32_t*)&x0);
                hhi[j] = silu_h2(*(uint32_t*)&x1);
            }
        }

        // ---- GEMM2 partial: acc2 += h[16,64] @ W2c^T (h in regs, B from global) ----
        const uint4* w2c = w2f + c * 512;
        #pragma unroll
        for (int kk = 0; kk < 4; kk++) {
            uint32_t a0 = hlo[2 * kk], a1 = hhi[2 * kk];
            uint32_t a2 = hlo[2 * kk + 1], a3 = hhi[2 * kk + 1];
            #pragma unroll
            for (int jp = 0; jp < 4; jp++) {
                uint4 f = __ldg(w2c + (kk * 4 + jp) * 32);
                mma16816(acc2[2 * jp],     a0, a1, a2, a3, f.x, f.y);
                mma16816(acc2[2 * jp + 1], a0, a1, a2, a3, f.z, f.w);
            }
        }
    }

    // ---- epilogue2: + b2, store ----
    {
        float* olo = out + ((size_t)(b * NQ + q0 + qi_lo) * NK + (k0 + ki)) * DOUT;
        float* ohi = olo + (size_t)NK * DOUT;                // qi + 1
        #pragma unroll
        for (int j = 0; j < 8; j++) {
            int n = j * 8 + cp;
            float2 v0, v1;
            v0.x = acc2[j][0] + sb2[n];
            v0.y = acc2[j][1] + sb2[n + 1];
            v1.x = acc2[j][2] + sb2[n];
            v1.y = acc2[j][3] + sb2[n + 1];
            *(float2*)(olo + n) = v0;
            *(float2*)(ohi + n) = v1;
        }
    }
}

// ---------------------------------------------------------------------------
extern "C" void kernel_launch(void* const* d_in, const int* in_sizes, int n_in,
                              void* d_out, int out_size)
{
    const float* q_equi = (const float*)d_in[0];
    const float* q_inv  = (const float*)d_in[1];
    const float* k_equi = (const float*)d_in[2];
    const float* k_inv  = (const float*)d_in[3];
    const float* Wq     = (const float*)d_in[4];
    const float* bq     = (const float*)d_in[5];
    const float* Wk     = (const float*)d_in[6];
    const float* bk     = (const float*)d_in[7];
    const float* W1     = (const float*)d_in[8];
    const float* b1     = (const float*)d_in[9];
    const float* W2     = (const float*)d_in[10];
    const float* b2     = (const float*)d_in[11];
    float* out = (float*)d_out;

    cudaFuncSetAttribute(pair_kernel, cudaFuncAttributeMaxDynamicSharedMemorySize, SMEM_BYTES);

    prelude_kernel<<<NPRE + NPREP, 256>>>(q_inv, k_inv, Wq, bq, Wk, bk, W1, b1, W2);

    dim3 grid(NK / TK, NQ / TQ, BB);
    pair_kernel<<<grid, 256, SMEM_BYTES>>>(q_equi, k_equi, b2, out);
}

// round 10
// speedup vs baseline: 1.0320x; 1.0320x over previous
#include <cuda_runtime.h>
#include <cuda_fp16.h>
#include <cstdint>

// ---------------- problem constants ----------------
#define BB    4
#define NQ    384
#define NK    384
#define DE    64
#define DMSG  64
#define DFF   256
#define DOUT  64
#define DINV  256

#define TQ    16
#define TK    8
#define TM    128
#define NTILES (BB * (NQ/TQ) * (NK/TK))   // 4608
#define GRIDX  296                        // 148 SMs * 2 CTAs

#define LDA   136          // half pitch for W1 chunk tiles (k=128 + 8 pad)
#define LDH   72           // half pitch for W2 chunk tiles (k=64 + 8 pad)
#define LDAQ  260          // float pitch for sAq/sAk
#define LDKE  212          // float pitch for k-equi staging (bank-spread)

#define NPRE  (BB * (NQ + NK))
#define NPREP 96

// ---------------- device scratch ----------------
__device__ float g_Aq[BB * NQ * DFF];
__device__ float g_Ak[BB * NK * DFF];
__device__ __align__(16) __half g_W1T[DFF * LDA];   // [n=256][pitch 136]
__device__ __align__(16) __half g_W2T[DOUT * 264];  // [n=64][pitch 264]

// ---------------- SMEM map (bytes) ----------------
#define OFF_QE    0        // 16*192*4 = 12288
#define OFF_KE    12288    //  8*212*4 =  6784
#define OFF_AQ    19072    // 16*260*4 = 16640
#define OFF_AK    35712    //  8*260*4 =  8320
#define OFF_W1C0  44032    // 17408
#define OFF_W1C1  61440    // 17408
#define OFF_W2C0  78848    //  9216
#define OFF_W2C1  88064    //  9216
#define OFF_B2    97280    //   256
#define SMEM_BYTES 97536

__device__ __forceinline__ uint32_t smem_u32(const void* p) {
    uint32_t a;
    asm("{ .reg .u64 t; cvta.to.shared.u64 t, %1; cvt.u32.u64 %0, t; }" : "=r"(a) : "l"(p));
    return a;
}
#define CP_ASYNC16(dst, src) \
    asm volatile("cp.async.cg.shared.global [%0], [%1], 16;" :: "r"(dst), "l"(src))
#define CP_COMMIT() asm volatile("cp.async.commit_group;" ::: "memory")
#define CP_WAIT(n)  asm volatile("cp.async.wait_group %0;" :: "n"(n) : "memory")

__device__ __forceinline__ void ldsm4(uint32_t& r0, uint32_t& r1, uint32_t& r2, uint32_t& r3,
                                      uint32_t addr) {
    asm volatile("ldmatrix.sync.aligned.m8n8.x4.shared.b16 {%0,%1,%2,%3}, [%4];"
        : "=r"(r0), "=r"(r1), "=r"(r2), "=r"(r3) : "r"(addr));
}
__device__ __forceinline__ void mma16816(float* c, uint32_t a0, uint32_t a1, uint32_t a2,
                                         uint32_t a3, uint32_t b0, uint32_t b1) {
    asm volatile(
        "mma.sync.aligned.m16n8k16.row.col.f32.f16.f16.f32 "
        "{%0,%1,%2,%3}, {%4,%5,%6,%7}, {%8,%9}, {%0,%1,%2,%3};"
        : "+f"(c[0]), "+f"(c[1]), "+f"(c[2]), "+f"(c[3])
        : "r"(a0), "r"(a1), "r"(a2), "r"(a3), "r"(b0), "r"(b1));
}
__device__ __forceinline__ uint32_t silu_h2(uint32_t xu) {
    uint32_t hxu, tu, res;
    asm("mul.rn.f16x2 %0, %1, %2;" : "=r"(hxu) : "r"(xu), "r"(0x38003800u));
    asm("tanh.approx.f16x2 %0, %1;" : "=r"(tu) : "r"(hxu));
    asm("fma.rn.f16x2 %0, %1, %2, %3;" : "=r"(res) : "r"(hxu), "r"(tu), "r"(hxu));
    return res;
}

// ---------------- prelude: A_q / A_k (+ appended weight-prep) ----------------
__global__ void __launch_bounds__(256) prelude_kernel(
    const float* __restrict__ q_inv, const float* __restrict__ k_inv,
    const float* __restrict__ Wq, const float* __restrict__ bq,
    const float* __restrict__ Wk, const float* __restrict__ bk,
    const float* __restrict__ W1, const float* __restrict__ b1,
    const float* __restrict__ W2)
{
    int blk = blockIdx.x;

    if (blk >= NPRE) {
        int idx = (blk - NPRE) * 256 + threadIdx.x;
        int total = DFF * 128 + DOUT * DFF;
        for (; idx < total; idx += NPREP * 256) {
            if (idx < DFF * 128) {
                int n = idx >> 7, k = idx & 127;
                g_W1T[n * LDA + k] = __float2half(W1[(128 + k) * DFF + n]);
            } else {
                int j = idx - DFF * 128;
                int n = j >> 8, k = j & 255;
                g_W2T[n * 264 + k] = __float2half(W2[k * DOUT + n]);
            }
        }
        return;
    }

    bool isQ = blk < BB * NQ;
    int bn = isQ ? blk : blk - BB * NQ;

    const float* inv  = isQ ? (q_inv + bn * DINV) : (k_inv + bn * DINV);
    const float* W    = isQ ? Wq : Wk;
    const float* bias = isQ ? bq : bk;
    const float* W1s  = isQ ? W1 : (W1 + DMSG * DFF);
    float* A          = isQ ? (g_Aq + bn * DFF) : (g_Ak + bn * DFF);

    __shared__ float s_inv[DINV];
    __shared__ float s_part[4][DMSG];
    __shared__ float s_msg[DMSG];

    int tid = threadIdx.x;
    s_inv[tid] = inv[tid];
    __syncthreads();

    int m = tid & 63, g = tid >> 6;
    float acc = 0.f;
    #pragma unroll 16
    for (int i = g * 64; i < g * 64 + 64; i++)
        acc = fmaf(s_inv[i], W[i * DMSG + m], acc);
    s_part[g][m] = acc;
    __syncthreads();
    if (tid < DMSG)
        s_msg[tid] = s_part[0][tid] + s_part[1][tid] + s_part[2][tid] + s_part[3][tid] + bias[tid];
    __syncthreads();

    float a = isQ ? b1[tid] : 0.f;
    #pragma unroll 32
    for (int mm = 0; mm < DMSG; mm++)
        a = fmaf(s_msg[mm], W1s[mm * DFF + tid], a);
    A[tid] = a;
}

// ---------------- staging helpers ----------------
__device__ __forceinline__ void prefetch_w(int c, uint32_t w1dst, uint32_t w2dst, int tid) {
    const char* src1 = (const char*)(g_W1T + c * 64 * LDA);
    #pragma unroll
    for (int i = tid; i < 1088; i += 256)
        CP_ASYNC16(w1dst + i * 16, src1 + i * 16);
    #pragma unroll
    for (int i = tid; i < 512; i += 256) {
        int row = i >> 3, seg = i & 7;
        CP_ASYNC16(w2dst + (row * LDH + seg * 8) * 2,
                   (const char*)(g_W2T + row * 264 + c * 64 + seg * 8));
    }
}

__device__ __forceinline__ void stage_equi(uint32_t sb, const float* q_equi,
                                           const float* k_equi, int b, int q0, int k0,
                                           int tid) {
    const char* qsrc = (const char*)(q_equi + (size_t)(b * NQ + q0) * 192);
    const char* ksrc = (const char*)(k_equi + (size_t)(b * NK + k0) * 192);
    #pragma unroll
    for (int i = tid; i < 768; i += 256)
        CP_ASYNC16(sb + OFF_QE + i * 16, qsrc + i * 16);
    for (int i = tid; i < 384; i += 256) {
        int row = i / 48, seg = i - row * 48;
        CP_ASYNC16(sb + OFF_KE + row * (LDKE * 4) + seg * 16,
                   ksrc + (row * 192 + seg * 4) * 4);
    }
}

__device__ __forceinline__ void stage_aqak(uint32_t sb, int b, int q0, int k0, int tid) {
    const char* aqsrc = (const char*)(g_Aq + (size_t)(b * NQ + q0) * DFF);
    const char* aksrc = (const char*)(g_Ak + (size_t)(b * NK + k0) * DFF);
    #pragma unroll
    for (int i = tid; i < 1024; i += 256) {
        int row = i >> 6, c4 = i & 63;
        CP_ASYNC16(sb + OFF_AQ + (row * LDAQ + c4 * 4) * 4, aqsrc + i * 16);
    }
    #pragma unroll
    for (int i = tid; i < 512; i += 256) {
        int row = i >> 6, c4 = i & 63;
        CP_ASYNC16(sb + OFF_AK + (row * LDAQ + c4 * 4) * 4, aksrc + i * 16);
    }
}

__device__ __forceinline__ void decode_tile(int t, int& b, int& q0, int& k0) {
    b = t / ((NQ / TQ) * (NK / TK));
    int rr = t % ((NQ / TQ) * (NK / TK));
    q0 = (rr / (NK / TK)) * TQ;
    k0 = (rr % (NK / TK)) * TK;
}

// ---------------- persistent pairwise kernel (2 CTAs/SM) ----------------
__global__ void __launch_bounds__(256, 2) pair_kernel(
    const float* __restrict__ q_equi, const float* __restrict__ k_equi,
    const float* __restrict__ b2, float* __restrict__ out)
{
    extern __shared__ char smem[];
    const uint32_t sb = smem_u32(smem);
    int tid = threadIdx.x;
    int w = tid >> 5, lane = tid & 31;

    float* sAq = (float*)(smem + OFF_AQ);
    float* sAk = (float*)(smem + OFF_AK);
    float* sb2 = (float*)(smem + OFF_B2);

    // lane geometry
    const int r = lane >> 2, cp = (lane & 3) * 2;
    const int qi0 = 2 * w;                 // q-row of m_lo; m_hi is qi0+1; k-row = r

    // B-side ldmatrix bases (per W buffer)
    const int bRow = (lane & 7) + ((lane >> 4) << 3);
    const uint32_t bOff1 = (bRow * LDA + ((lane >> 3) & 1) * 8) * 2;
    const uint32_t bOff2 = (bRow * LDH + ((lane >> 3) & 1) * 8) * 2;
    const uint32_t b1Base[2] = { sb + OFF_W1C0 + bOff1, sb + OFF_W1C1 + bOff1 };
    const uint32_t b2Base[2] = { sb + OFF_W2C0 + bOff2, sb + OFF_W2C1 + bOff2 };
    const uint32_t w1Dst[2]  = { sb + OFF_W1C0, sb + OFF_W1C1 };
    const uint32_t w2Dst[2]  = { sb + OFF_W2C0, sb + OFF_W2C1 };

    // ---- prologue: stage first tile's inputs ----
    int t0 = blockIdx.x;
    int b_, q0_, k0_;
    decode_tile(t0, b_, q0_, k0_);
    stage_equi(sb, q_equi, k_equi, b_, q0_, k0_, tid);
    if (tid < 16) CP_ASYNC16(sb + OFF_B2 + tid * 16, (const char*)b2 + tid * 16);
    CP_COMMIT();                                   // G: equi(t0)+b2
    prefetch_w(0, w1Dst[0], w2Dst[0], tid);
    CP_COMMIT();                                   // G: Wc0
    stage_aqak(sb, b_, q0_, k0_, tid);
    CP_COMMIT();                                   // G: AQAK(t0)

    // ================= persistent tile loop =================
    for (int t = blockIdx.x; t < NTILES; t += GRIDX) {
        int b, q0, k0;
        decode_tile(t, b, q0, k0);
        int tn = (t + GRIDX < NTILES) ? (t + GRIDX) : t;
        int bn, q0n, k0n;
        decode_tile(tn, bn, q0n, k0n);

        // P1: equi(t) + Wc0(t) arrived (AQAK(t) may still fly)
        CP_WAIT(1);
        __syncthreads();

        // P2: dot & dist -> A fragments directly in registers
        uint32_t af[8][4];
        {
            const float* q0p = (const float*)(smem + OFF_QE) + qi0 * 192;
            const float* q1p = q0p + 192;
            const float* kp  = (const float*)(smem + OFF_KE) + r * LDKE;
            #pragma unroll
            for (int ww = 0; ww < 4; ww++) {
                #pragma unroll
                for (int hh = 0; hh < 2; hh++) {
                    int e0 = ww * 16 + hh * 8 + cp;
                    float2 k0v = *(const float2*)(kp + e0);
                    float2 k1v = *(const float2*)(kp + e0 + 64);
                    float2 k2v = *(const float2*)(kp + e0 + 128);
                    // row m_lo (q-row qi0)
                    {
                        float2 a0 = *(const float2*)(q0p + e0);
                        float2 a1 = *(const float2*)(q0p + e0 + 64);
                        float2 a2 = *(const float2*)(q0p + e0 + 128);
                        float dx = a0.x * k0v.x + a1.x * k1v.x + a2.x * k2v.x;
                        float dy = a0.y * k0v.y + a1.y * k1v.y + a2.y * k2v.y;
                        float fx0 = a0.x - k0v.x, fx1 = a1.x - k1v.x, fx2 = a2.x - k2v.x;
                        float fy0 = a0.y - k0v.y, fy1 = a1.y - k1v.y, fy2 = a2.y - k2v.y;
                        float sx = sqrtf(fx0 * fx0 + fx1 * fx1 + fx2 * fx2);
                        float sy = sqrtf(fy0 * fy0 + fy1 * fy1 + fy2 * fy2);
                        __half2 hd = __floats2half2_rn(dx, dy);
                        __half2 hs = __floats2half2_rn(sx, sy);
                        af[ww][hh * 2 + 0]     = *(uint32_t*)&hd;
                        af[ww + 4][hh * 2 + 0] = *(uint32_t*)&hs;
                    }
                    // row m_hi (q-row qi0+1)
                    {
                        float2 a0 = *(const float2*)(q1p + e0);
                        float2 a1 = *(const float2*)(q1p + e0 + 64);
                        float2 a2 = *(const float2*)(q1p + e0 + 128);
                        float dx = a0.x * k0v.x + a1.x * k1v.x + a2.x * k2v.x;
                        float dy = a0.y * k0v.y + a1.y * k1v.y + a2.y * k2v.y;
                        float fx0 = a0.x - k0v.x, fx1 = a1.x - k1v.x, fx2 = a2.x - k2v.x;
                        float fy0 = a0.y - k0v.y, fy1 = a1.y - k1v.y, fy2 = a2.y - k2v.y;
                        float sx = sqrtf(fx0 * fx0 + fx1 * fx1 + fx2 * fx2);
                        float sy = sqrtf(fy0 * fy0 + fy1 * fy1 + fy2 * fy2);
                        __half2 hd = __floats2half2_rn(dx, dy);
                        __half2 hs = __floats2half2_rn(sx, sy);
                        af[ww][hh * 2 + 1]     = *(uint32_t*)&hd;
                        af[ww + 4][hh * 2 + 1] = *(uint32_t*)&hs;
                    }
                }
            }
        }

        // P3: AQAK(t) visible to all; all warps done reading equi
        CP_WAIT(0);
        __syncthreads();

        float acc2[8][4];
        #pragma unroll
        for (int j = 0; j < 8; j++)
            #pragma unroll
            for (int i = 0; i < 4; i++) acc2[j][i] = 0.f;

        // ---- chunk loop over N (4 x 64), W double-buffered, input prefetch woven in ----
        #pragma unroll
        for (int c = 0; c < 4; c++) {
            if (c > 0) {                         // wait for W chunk c
                if (c < 3) { CP_WAIT(0); }       // pending: [Wc]
                else       { CP_WAIT(1); }       // pending: [Wc3, equi'] -> Wc3 done
                __syncthreads();
            }
            // prefetch next W chunk into the other buffer
            prefetch_w((c + 1) & 3, w1Dst[(c + 1) & 1], w2Dst[(c + 1) & 1], tid);
            CP_COMMIT();
            if (c == 2) {                        // prefetch next tile's equi after Wc3
                stage_equi(sb, q_equi, k_equi, bn, q0n, k0n, tid);
                CP_COMMIT();
            }

            const uint32_t bA1 = b1Base[c & 1];
            const uint32_t bA2 = b2Base[c & 1];

            // GEMM1 chunk
            float acc1[8][4];
            #pragma unroll
            for (int j = 0; j < 8; j++)
                #pragma unroll
                for (int i = 0; i < 4; i++) acc1[j][i] = 0.f;

            #pragma unroll
            for (int kk = 0; kk < 8; kk++) {
                #pragma unroll
                for (int jp = 0; jp < 4; jp++) {
                    uint32_t b0, b1r, b2r, b3;
                    ldsm4(b0, b1r, b2r, b3, bA1 + jp * 16 * LDA * 2 + kk * 32);
                    mma16816(acc1[2 * jp],     af[kk][0], af[kk][1], af[kk][2], af[kk][3], b0,  b1r);
                    mma16816(acc1[2 * jp + 1], af[kk][0], af[kk][1], af[kk][2], af[kk][3], b2r, b3);
                }
            }

            // epilogue1: + Aq + Ak (ak shared lo/hi), SiLU -> register h fragments
            uint32_t hlo[8], hhi[8];
            {
                const float* aqlo = sAq + qi0 * LDAQ + c * 64;
                const float* aqhi = aqlo + LDAQ;
                const float* akr  = sAk + r * LDAQ + c * 64;
                #pragma unroll
                for (int j = 0; j < 8; j++) {
                    int n = j * 8 + cp;
                    float2 aql = *(const float2*)(aqlo + n);
                    float2 aqh = *(const float2*)(aqhi + n);
                    float2 akl = *(const float2*)(akr + n);
                    float v0 = acc1[j][0] + aql.x + akl.x;
                    float v1 = acc1[j][1] + aql.y + akl.y;
                    float v2 = acc1[j][2] + aqh.x + akl.x;
                    float v3 = acc1[j][3] + aqh.y + akl.y;
                    __half2 x0 = __floats2half2_rn(v0, v1);
                    __half2 x1 = __floats2half2_rn(v2, v3);
                    hlo[j] = silu_h2(*(uint32_t*)&x0);
                    hhi[j] = silu_h2(*(uint32_t*)&x1);
                }
            }

            // GEMM2 partial (h in registers)
            #pragma unroll
            for (int kk = 0; kk < 4; kk++) {
                uint32_t a0 = hlo[2 * kk], a1 = hhi[2 * kk];
                uint32_t a2 = hlo[2 * kk + 1], a3 = hhi[2 * kk + 1];
                #pragma unroll
                for (int jp = 0; jp < 4; jp++) {
                    uint32_t b0, b1r, b2r, b3;
                    ldsm4(b0, b1r, b2r, b3, bA2 + jp * 16 * LDH * 2 + kk * 32);
                    mma16816(acc2[2 * jp],     a0, a1, a2, a3, b0,  b1r);
                    mma16816(acc2[2 * jp + 1], a0, a1, a2, a3, b2r, b3);
                }
            }
        }

        // POST: all epilogue1 reads of sAq/sAk done -> prefetch next tile's Aq/Ak
        __syncthreads();
        stage_aqak(sb, bn, q0n, k0n, tid);
        CP_COMMIT();

        // epilogue2: + b2, store
        {
            float* olo = out + ((size_t)(b * NQ + q0 + qi0) * NK + (k0 + r)) * DOUT;
            float* ohi = olo + (size_t)NK * DOUT;
            #pragma unroll
            for (int j = 0; j < 8; j++) {
                int n = j * 8 + cp;
                float2 v0, v1;
                v0.x = acc2[j][0] + sb2[n];
                v0.y = acc2[j][1] + sb2[n + 1];
                v1.x = acc2[j][2] + sb2[n];
                v1.y = acc2[j][3] + sb2[n + 1];
                *(float2*)(olo + n) = v0;
                *(float2*)(ohi + n) = v1;
            }
        }
    }

    // drain outstanding async copies before exit
    CP_WAIT(0);
    __syncthreads();
}

// ---------------------------------------------------------------------------
extern "C" void kernel_launch(void* const* d_in, const int* in_sizes, int n_in,
                              void* d_out, int out_size)
{
    const float* q_equi = (const float*)d_in[0];
    const float* q_inv  = (const float*)d_in[1];
    const float* k_equi = (const float*)d_in[2];
    const float* k_inv  = (const float*)d_in[3];
    const float* Wq     = (const float*)d_in[4];
    const float* bq     = (const float*)d_in[5];
    const float* Wk     = (const float*)d_in[6];
    const float* bk     = (const float*)d_in[7];
    const float* W1     = (const float*)d_in[8];
    const float* b1     = (const float*)d_in[9];
    const float* W2     = (const float*)d_in[10];
    const float* b2     = (const float*)d_in[11];
    float* out = (float*)d_out;

    cudaFuncSetAttribute(pair_kernel, cudaFuncAttributeMaxDynamicSharedMemorySize, SMEM_BYTES);

    prelude_kernel<<<NPRE + NPREP, 256>>>(q_inv, k_inv, Wq, bq, Wk, bk, W1, b1, W2);

    pair_kernel<<<GRIDX, 256, SMEM_BYTES>>>(q_equi, k_equi, b2, out);
}

// round 12
// speedup vs baseline: 1.1106x; 1.0762x over previous
#include <cuda_runtime.h>
#include <cuda_fp16.h>
#include <cstdint>

// ---------------- problem constants ----------------
#define BB    4
#define NQ    384
#define NK    384
#define DE    64
#define DMSG  64
#define DFF   256
#define DOUT  64
#define DINV  256

#define TQ    16
#define TK    8
#define TM    128

#define LDA   136          // half pitch for W1 chunk tiles (k=128 + 8 pad)
#define LDH   72           // half pitch for W2 chunk tiles (k=64 + 8 pad)
#define LDKE  212          // float pitch for k-equi staging (bank-spread)
#define LDAQH 264          // half pitch for sAqh/sAkh (row stride 528 B = 132 floats ≡ 4 mod 32)

#define NPRE  (BB * (NQ + NK))
#define NPREP 96

// ---------------- device scratch ----------------
__device__ __half g_Aqh[BB * NQ * DFF];
__device__ __half g_Akh[BB * NK * DFF];
__device__ __align__(16) __half g_W1T[DFF * LDA];   // [n=256][pitch 136]
__device__ __align__(16) __half g_W2T[DOUT * 264];  // [n=64][pitch 264]

// ---------------- SMEM map (bytes) ----------------
#define OFF_QE    0        // 16*192*4 = 12288
#define OFF_KE    12288    //  8*212*4 =  6784
#define OFF_AQH   19072    // 16*264*2 =  8448
#define OFF_AKH   27520    //  8*264*2 =  4224
#define OFF_W1C0  31744    // 17408
#define OFF_W1C1  49152    // 17408
#define OFF_W2C0  66560    //  9216
#define OFF_W2C1  75776    //  9216
#define OFF_B2    84992    //   256
#define SMEM_BYTES 85248

__device__ __forceinline__ uint32_t smem_u32(const void* p) {
    uint32_t a;
    asm("{ .reg .u64 t; cvta.to.shared.u64 t, %1; cvt.u32.u64 %0, t; }" : "=r"(a) : "l"(p));
    return a;
}
#define CP_ASYNC16(dst, src) \
    asm volatile("cp.async.cg.shared.global [%0], [%1], 16;" :: "r"(dst), "l"(src))
#define CP_COMMIT() asm volatile("cp.async.commit_group;" ::: "memory")
#define CP_WAIT(n)  asm volatile("cp.async.wait_group %0;" :: "n"(n) : "memory")

__device__ __forceinline__ void ldsm4(uint32_t& r0, uint32_t& r1, uint32_t& r2, uint32_t& r3,
                                      uint32_t addr) {
    asm volatile("ldmatrix.sync.aligned.m8n8.x4.shared.b16 {%0,%1,%2,%3}, [%4];"
        : "=r"(r0), "=r"(r1), "=r"(r2), "=r"(r3) : "r"(addr));
}
__device__ __forceinline__ void mma16816(float* c, uint32_t a0, uint32_t a1, uint32_t a2,
                                         uint32_t a3, uint32_t b0, uint32_t b1) {
    asm volatile(
        "mma.sync.aligned.m16n8k16.row.col.f32.f16.f16.f32 "
        "{%0,%1,%2,%3}, {%4,%5,%6,%7}, {%8,%9}, {%0,%1,%2,%3};"
        : "+f"(c[0]), "+f"(c[1]), "+f"(c[2]), "+f"(c[3])
        : "r"(a0), "r"(a1), "r"(a2), "r"(a3), "r"(b0), "r"(b1));
}
__device__ __forceinline__ uint32_t silu_h2(uint32_t xu) {
    uint32_t hxu, tu, res;
    asm("mul.rn.f16x2 %0, %1, %2;" : "=r"(hxu) : "r"(xu), "r"(0x38003800u));
    asm("tanh.approx.f16x2 %0, %1;" : "=r"(tu) : "r"(hxu));
    asm("fma.rn.f16x2 %0, %1, %2, %3;" : "=r"(res) : "r"(hxu), "r"(tu), "r"(hxu));
    return res;
}

// ---------------- prelude: A_q / A_k (fp16 output) + appended weight-prep ----------------
__global__ void __launch_bounds__(256) prelude_kernel(
    const float* __restrict__ q_inv, const float* __restrict__ k_inv,
    const float* __restrict__ Wq, const float* __restrict__ bq,
    const float* __restrict__ Wk, const float* __restrict__ bk,
    const float* __restrict__ W1, const float* __restrict__ b1,
    const float* __restrict__ W2)
{
    int blk = blockIdx.x;

    if (blk >= NPRE) {
        int idx = (blk - NPRE) * 256 + threadIdx.x;
        int total = DFF * 128 + DOUT * DFF;
        for (; idx < total; idx += NPREP * 256) {
            if (idx < DFF * 128) {
                int n = idx >> 7, k = idx & 127;
                g_W1T[n * LDA + k] = __float2half(W1[(128 + k) * DFF + n]);
            } else {
                int j = idx - DFF * 128;
                int n = j >> 8, k = j & 255;
                g_W2T[n * 264 + k] = __float2half(W2[k * DOUT + n]);
            }
        }
        return;
    }

    bool isQ = blk < BB * NQ;
    int bn = isQ ? blk : blk - BB * NQ;

    const float* inv  = isQ ? (q_inv + bn * DINV) : (k_inv + bn * DINV);
    const float* W    = isQ ? Wq : Wk;
    const float* bias = isQ ? bq : bk;
    const float* W1s  = isQ ? W1 : (W1 + DMSG * DFF);
    __half* A         = isQ ? (g_Aqh + bn * DFF) : (g_Akh + bn * DFF);

    __shared__ float s_inv[DINV];
    __shared__ float s_part[4][DMSG];
    __shared__ float s_msg[DMSG];

    int tid = threadIdx.x;
    s_inv[tid] = inv[tid];
    __syncthreads();

    int m = tid & 63, g = tid >> 6;
    float acc = 0.f;
    #pragma unroll 16
    for (int i = g * 64; i < g * 64 + 64; i++)
        acc = fmaf(s_inv[i], W[i * DMSG + m], acc);
    s_part[g][m] = acc;
    __syncthreads();
    if (tid < DMSG)
        s_msg[tid] = s_part[0][tid] + s_part[1][tid] + s_part[2][tid] + s_part[3][tid] + bias[tid];
    __syncthreads();

    float a = isQ ? b1[tid] : 0.f;
    #pragma unroll 32
    for (int mm = 0; mm < DMSG; mm++)
        a = fmaf(s_msg[mm], W1s[mm * DFF + tid], a);
    A[tid] = __float2half(a);
}

// ---------------- W chunk prefetch via cp.async ----------------
__device__ __forceinline__ void prefetch_w(int c, uint32_t w1dst, uint32_t w2dst, int tid) {
    const char* src1 = (const char*)(g_W1T + c * 64 * LDA);
    #pragma unroll
    for (int i = tid; i < 1088; i += 256)
        CP_ASYNC16(w1dst + i * 16, src1 + i * 16);
    #pragma unroll
    for (int i = tid; i < 512; i += 256) {
        int row = i >> 3, seg = i & 7;
        CP_ASYNC16(w2dst + (row * LDH + seg * 8) * 2,
                   (const char*)(g_W2T + row * 264 + c * 64 + seg * 8));
    }
}

// ---------------- main pairwise kernel (2 CTAs/SM) ----------------
__global__ void __launch_bounds__(256, 2) pair_kernel(
    const float* __restrict__ q_equi, const float* __restrict__ k_equi,
    const float* __restrict__ b2, float* __restrict__ out)
{
    extern __shared__ char smem[];
    const uint32_t sb = smem_u32(smem);
    int tid = threadIdx.x;
    int w = tid >> 5, lane = tid & 31;

    int b  = blockIdx.z;
    int q0 = blockIdx.y * TQ;
    int k0 = blockIdx.x * TK;

    const __half* sAqh = (const __half*)(smem + OFF_AQH);
    const __half* sAkh = (const __half*)(smem + OFF_AKH);
    const float*  sb2  = (const float*)(smem + OFF_B2);

    // ---- phase 0: async-stage equi (f32), Aq/Ak (f16, 32 segs/row!), b2; prefetch W chunk0 ----
    {
        const char* qsrc = (const char*)(q_equi + (size_t)(b * NQ + q0) * 192);
        const char* ksrc = (const char*)(k_equi + (size_t)(b * NK + k0) * 192);
        #pragma unroll
        for (int i = tid; i < 768; i += 256)
            CP_ASYNC16(sb + OFF_QE + i * 16, qsrc + i * 16);
        for (int i = tid; i < 384; i += 256) {
            int row = i / 48, seg = i - row * 48;
            CP_ASYNC16(sb + OFF_KE + row * (LDKE * 4) + seg * 16,
                       ksrc + (row * 192 + seg * 4) * 4);
        }
        // Aq: 16 rows x 512B (32 segs of 16B); smem pitch 528B
        const char* aqsrc = (const char*)(g_Aqh + (size_t)(b * NQ + q0) * DFF);
        const char* aksrc = (const char*)(g_Akh + (size_t)(b * NK + k0) * DFF);
        #pragma unroll
        for (int i = tid; i < 512; i += 256) {
            int row = i >> 5, seg = i & 31;
            CP_ASYNC16(sb + OFF_AQH + row * (LDAQH * 2) + seg * 16, aqsrc + i * 16);
        }
        if (tid < 256) {                                   // 8 rows * 32 segs
            int row = tid >> 5, seg = tid & 31;
            CP_ASYNC16(sb + OFF_AKH + row * (LDAQH * 2) + seg * 16, aksrc + tid * 16);
        }
        if (tid < 16) CP_ASYNC16(sb + OFF_B2 + tid * 16, (const char*)b2 + tid * 16);
        CP_COMMIT();                                       // G0: inputs
        prefetch_w(0, sb + OFF_W1C0, sb + OFF_W2C0, tid);
        CP_COMMIT();                                       // G1: W chunk 0
        CP_WAIT(1);                                        // inputs landed
        __syncthreads();
    }

    // ---- lane geometry ----
    const int r = lane >> 2, cp = (lane & 3) * 2;
    const int qi0 = 2 * w;               // pair row m_lo = 16w + r -> (q=2w, k=r); m_hi -> (2w+1, r)

    // ---- P2: dot & dist -> GEMM1 A-fragments directly in registers ----
    uint32_t af[8][4];
    {
        const float* q0p = (const float*)(smem + OFF_QE) + qi0 * 192;
        const float* q1p = q0p + 192;
        const float* kp  = (const float*)(smem + OFF_KE) + r * LDKE;
        #pragma unroll
        for (int ww = 0; ww < 4; ww++) {
            #pragma unroll
            for (int hh = 0; hh < 2; hh++) {
                int e0 = ww * 16 + hh * 8 + cp;
                float2 k0v = *(const float2*)(kp + e0);
                float2 k1v = *(const float2*)(kp + e0 + 64);
                float2 k2v = *(const float2*)(kp + e0 + 128);
                {   // row m_lo (q-row qi0)
                    float2 a0 = *(const float2*)(q0p + e0);
                    float2 a1 = *(const float2*)(q0p + e0 + 64);
                    float2 a2 = *(const float2*)(q0p + e0 + 128);
                    float dx = a0.x * k0v.x + a1.x * k1v.x + a2.x * k2v.x;
                    float dy = a0.y * k0v.y + a1.y * k1v.y + a2.y * k2v.y;
                    float fx0 = a0.x - k0v.x, fx1 = a1.x - k1v.x, fx2 = a2.x - k2v.x;
                    float fy0 = a0.y - k0v.y, fy1 = a1.y - k1v.y, fy2 = a2.y - k2v.y;
                    float sx = sqrtf(fx0 * fx0 + fx1 * fx1 + fx2 * fx2);
                    float sy = sqrtf(fy0 * fy0 + fy1 * fy1 + fy2 * fy2);
                    __half2 hd = __floats2half2_rn(dx, dy);
                    __half2 hs = __floats2half2_rn(sx, sy);
                    af[ww][hh * 2 + 0]     = *(uint32_t*)&hd;
                    af[ww + 4][hh * 2 + 0] = *(uint32_t*)&hs;
                }
                {   // row m_hi (q-row qi0+1)
                    float2 a0 = *(const float2*)(q1p + e0);
                    float2 a1 = *(const float2*)(q1p + e0 + 64);
                    float2 a2 = *(const float2*)(q1p + e0 + 128);
                    float dx = a0.x * k0v.x + a1.x * k1v.x + a2.x * k2v.x;
                    float dy = a0.y * k0v.y + a1.y * k1v.y + a2.y * k2v.y;
                    float fx0 = a0.x - k0v.x, fx1 = a1.x - k1v.x, fx2 = a2.x - k2v.x;
                    float fy0 = a0.y - k0v.y, fy1 = a1.y - k1v.y, fy2 = a2.y - k2v.y;
                    float sx = sqrtf(fx0 * fx0 + fx1 * fx1 + fx2 * fx2);
                    float sy = sqrtf(fy0 * fy0 + fy1 * fy1 + fy2 * fy2);
                    __half2 hd = __floats2half2_rn(dx, dy);
                    __half2 hs = __floats2half2_rn(sx, sy);
                    af[ww][hh * 2 + 1]     = *(uint32_t*)&hd;
                    af[ww + 4][hh * 2 + 1] = *(uint32_t*)&hs;
                }
            }
        }
    }

    // B-side ldmatrix bases (per W buffer)
    const int bRow = (lane & 7) + ((lane >> 4) << 3);
    const uint32_t bOff1 = (bRow * LDA + ((lane >> 3) & 1) * 8) * 2;
    const uint32_t bOff2 = (bRow * LDH + ((lane >> 3) & 1) * 8) * 2;
    const uint32_t b1Base[2] = { sb + OFF_W1C0 + bOff1, sb + OFF_W1C1 + bOff1 };
    const uint32_t b2Base[2] = { sb + OFF_W2C0 + bOff2, sb + OFF_W2C1 + bOff2 };
    const uint32_t w1Dst[2]  = { sb + OFF_W1C0, sb + OFF_W1C1 };
    const uint32_t w2Dst[2]  = { sb + OFF_W2C0, sb + OFF_W2C1 };

    float acc2[8][4];
    #pragma unroll
    for (int j = 0; j < 8; j++)
        #pragma unroll
        for (int i = 0; i < 4; i++) acc2[j][i] = 0.f;

    // ================= chunk loop over N (4 x 64), W double-buffered =================
    for (int c = 0; c < 4; c++) {
        CP_WAIT(0);            // W chunk c resident
        __syncthreads();       // visible to all; other buffer free for reuse

        if (c < 3) {           // prefetch chunk c+1
            prefetch_w(c + 1, w1Dst[(c + 1) & 1], w2Dst[(c + 1) & 1], tid);
            CP_COMMIT();
        }

        const uint32_t bA1 = b1Base[c & 1];
        const uint32_t bA2 = b2Base[c & 1];

        // ---- GEMM1 chunk: acc1[16,64] = A[16,128] @ W1c^T ----
        float acc1[8][4];
        #pragma unroll
        for (int j = 0; j < 8; j++)
            #pragma unroll
            for (int i = 0; i < 4; i++) acc1[j][i] = 0.f;

        #pragma unroll
        for (int kk = 0; kk < 8; kk++) {
            #pragma unroll
            for (int jp = 0; jp < 4; jp++) {
                uint32_t b0, b1r, b2r, b3;
                ldsm4(b0, b1r, b2r, b3, bA1 + jp * 16 * LDA * 2 + kk * 32);
                mma16816(acc1[2 * jp],     af[kk][0], af[kk][1], af[kk][2], af[kk][3], b0,  b1r);
                mma16816(acc1[2 * jp + 1], af[kk][0], af[kk][1], af[kk][2], af[kk][3], b2r, b3);
            }
        }

        // ---- epilogue1: + Aq + Ak (fp16, ak shared lo/hi), SiLU -> register h frags ----
        uint32_t hlo[8], hhi[8];
        {
            const __half* aqlo = sAqh + qi0 * LDAQH + c * 64;
            const __half* aqhi = aqlo + LDAQH;
            const __half* akr  = sAkh + r * LDAQH + c * 64;
            #pragma unroll
            for (int j = 0; j < 8; j++) {
                int n = j * 8 + cp;
                float2 aql = __half22float2(*(const __half2*)(aqlo + n));
                float2 aqh = __half22float2(*(const __half2*)(aqhi + n));
                float2 akl = __half22float2(*(const __half2*)(akr + n));
                float v0 = acc1[j][0] + aql.x + akl.x;
                float v1 = acc1[j][1] + aql.y + akl.y;
                float v2 = acc1[j][2] + aqh.x + akl.x;
                float v3 = acc1[j][3] + aqh.y + akl.y;
                __half2 x0 = __floats2half2_rn(v0, v1);
                __half2 x1 = __floats2half2_rn(v2, v3);
                hlo[j] = silu_h2(*(uint32_t*)&x0);
                hhi[j] = silu_h2(*(uint32_t*)&x1);
            }
        }

        // ---- GEMM2 partial: acc2 += h[16,64] @ W2c^T (h in registers) ----
        #pragma unroll
        for (int kk = 0; kk < 4; kk++) {
            uint32_t a0 = hlo[2 * kk], a1 = hhi[2 * kk];
            uint32_t a2 = hlo[2 * kk + 1], a3 = hhi[2 * kk + 1];
            #pragma unroll
            for (int jp = 0; jp < 4; jp++) {
                uint32_t b0, b1r, b2r, b3;
                ldsm4(b0, b1r, b2r, b3, bA2 + jp * 16 * LDH * 2 + kk * 32);
                mma16816(acc2[2 * jp],     a0, a1, a2, a3, b0,  b1r);
                mma16816(acc2[2 * jp + 1], a0, a1, a2, a3, b2r, b3);
            }
        }
    }

    // ---- epilogue2: + b2, store ----
    {
        float* olo = out + ((size_t)(b * NQ + q0 + qi0) * NK + (k0 + r)) * DOUT;
        float* ohi = olo + (size_t)NK * DOUT;
        #pragma unroll
        for (int j = 0; j < 8; j++) {
            int n = j * 8 + cp;
            float2 v0, v1;
            v0.x = acc2[j][0] + sb2[n];
            v0.y = acc2[j][1] + sb2[n + 1];
            v1.x = acc2[j][2] + sb2[n];
            v1.y = acc2[j][3] + sb2[n + 1];
            *(float2*)(olo + n) = v0;
            *(float2*)(ohi + n) = v1;
        }
    }
}

// ---------------------------------------------------------------------------
extern "C" void kernel_launch(void* const* d_in, const int* in_sizes, int n_in,
                              void* d_out, int out_size)
{
    const float* q_equi = (const float*)d_in[0];
    const float* q_inv  = (const float*)d_in[1];
    const float* k_equi = (const float*)d_in[2];
    const float* k_inv  = (const float*)d_in[3];
    const float* Wq     = (const float*)d_in[4];
    const float* bq     = (const float*)d_in[5];
    const float* Wk     = (const float*)d_in[6];
    const float* bk     = (const float*)d_in[7];
    const float* W1     = (const float*)d_in[8];
    const float* b1     = (const float*)d_in[9];
    const float* W2     = (const float*)d_in[10];
    const float* b2     = (const float*)d_in[11];
    float* out = (float*)d_out;

    cudaFuncSetAttribute(pair_kernel, cudaFuncAttributeMaxDynamicSharedMemorySize, SMEM_BYTES);

    prelude_kernel<<<NPRE + NPREP, 256>>>(q_inv, k_inv, Wq, bq, Wk, bk, W1, b1, W2);

    dim3 grid(NK / TK, NQ / TQ, BB);
    pair_kernel<<<grid, 256, SMEM_BYTES>>>(q_equi, k_equi, b2, out);
}

// round 13
// speedup vs baseline: 1.1249x; 1.0129x over previous
#include <cuda_runtime.h>
#include <cuda_fp16.h>
#include <cstdint>

// ---------------- problem constants ----------------
#define BB    4
#define NQ    384
#define NK    384
#define DE    64
#define DMSG  64
#define DFF   256
#define DOUT  64
#define DINV  256

#define TQ    16
#define TK    8
#define TM    128

#define LDA   136          // half pitch for W1 chunk tiles (k=128 + 8 pad)
#define LDH   72           // half pitch for W2 chunk tiles (k=64 + 8 pad)
#define LDKE  212          // float pitch for k-equi staging (bank-spread)
#define LDAQH 264          // half pitch for sAqh/sAkh

#define NPRE  (BB * (NQ + NK))
#define NPREP 96

// ---------------- device scratch ----------------
__device__ __half g_Aqh[BB * NQ * DFF];
__device__ __half g_Akh[BB * NK * DFF];
__device__ __align__(16) __half g_W1T[DFF * LDA];   // [n=256][pitch 136]
__device__ __align__(16) __half g_W2T[DOUT * 264];  // [n=64][pitch 264]

// ---------------- SMEM map (bytes) ----------------
#define OFF_QE    0        // 16*192*4 = 12288
#define OFF_KE    12288    //  8*212*4 =  6784
#define OFF_AQH   19072    // 16*264*2 =  8448
#define OFF_AKH   27520    //  8*264*2 =  4224
#define OFF_W1C0  31744    // 17408
#define OFF_W1C1  49152    // 17408
#define OFF_W2C0  66560    //  9216
#define OFF_W2C1  75776    //  9216
#define OFF_B2    84992    //   256
#define SMEM_BYTES 85248

__device__ __forceinline__ uint32_t smem_u32(const void* p) {
    uint32_t a;
    asm("{ .reg .u64 t; cvta.to.shared.u64 t, %1; cvt.u32.u64 %0, t; }" : "=r"(a) : "l"(p));
    return a;
}
#define CP_ASYNC16(dst, src) \
    asm volatile("cp.async.cg.shared.global [%0], [%1], 16;" :: "r"(dst), "l"(src))
#define CP_COMMIT() asm volatile("cp.async.commit_group;" ::: "memory")
#define CP_WAIT(n)  asm volatile("cp.async.wait_group %0;" :: "n"(n) : "memory")

__device__ __forceinline__ void ldsm4(uint32_t& r0, uint32_t& r1, uint32_t& r2, uint32_t& r3,
                                      uint32_t addr) {
    asm volatile("ldmatrix.sync.aligned.m8n8.x4.shared.b16 {%0,%1,%2,%3}, [%4];"
        : "=r"(r0), "=r"(r1), "=r"(r2), "=r"(r3) : "r"(addr));
}
__device__ __forceinline__ void mma16816(float* c, uint32_t a0, uint32_t a1, uint32_t a2,
                                         uint32_t a3, uint32_t b0, uint32_t b1) {
    asm volatile(
        "mma.sync.aligned.m16n8k16.row.col.f32.f16.f16.f32 "
        "{%0,%1,%2,%3}, {%4,%5,%6,%7}, {%8,%9}, {%0,%1,%2,%3};"
        : "+f"(c[0]), "+f"(c[1]), "+f"(c[2]), "+f"(c[3])
        : "r"(a0), "r"(a1), "r"(a2), "r"(a3), "r"(b0), "r"(b1));
}
__device__ __forceinline__ uint32_t silu_h2(uint32_t xu) {
    uint32_t hxu, tu, res;
    asm("mul.rn.f16x2 %0, %1, %2;" : "=r"(hxu) : "r"(xu), "r"(0x38003800u));
    asm("tanh.approx.f16x2 %0, %1;" : "=r"(tu) : "r"(hxu));
    asm("fma.rn.f16x2 %0, %1, %2, %3;" : "=r"(res) : "r"(hxu), "r"(tu), "r"(hxu));
    return res;
}

// ---------------- packed f32x2 helpers (sm_100+ baseline PTX) ----------------
__device__ __forceinline__ uint64_t pk2(float2 v) {
    uint64_t r; asm("mov.b64 %0, {%1, %2};" : "=l"(r) : "f"(v.x), "f"(v.y)); return r;
}
__device__ __forceinline__ float2 upk2(uint64_t v) {
    float2 r; asm("mov.b64 {%0, %1}, %2;" : "=f"(r.x), "=f"(r.y) : "l"(v)); return r;
}
__device__ __forceinline__ uint64_t mul2_(uint64_t a, uint64_t b) {
    uint64_t d; asm("mul.rn.f32x2 %0, %1, %2;" : "=l"(d) : "l"(a), "l"(b)); return d;
}
__device__ __forceinline__ uint64_t add2_(uint64_t a, uint64_t b) {
    uint64_t d; asm("add.rn.f32x2 %0, %1, %2;" : "=l"(d) : "l"(a), "l"(b)); return d;
}
__device__ __forceinline__ uint64_t fma2_(uint64_t a, uint64_t b, uint64_t c) {
    uint64_t d; asm("fma.rn.f32x2 %0, %1, %2, %3;" : "=l"(d) : "l"(a), "l"(b), "l"(c)); return d;
}
__device__ __forceinline__ float sqrt_ap(float x) {
    float r; asm("sqrt.approx.f32 %0, %1;" : "=f"(r) : "f"(x)); return r;
}
#define NEGMASK2 0x8000000080000000ULL

// ---------------- prelude: A_q / A_k (fp16 output) + appended weight-prep ----------------
__global__ void __launch_bounds__(256) prelude_kernel(
    const float* __restrict__ q_inv, const float* __restrict__ k_inv,
    const float* __restrict__ Wq, const float* __restrict__ bq,
    const float* __restrict__ Wk, const float* __restrict__ bk,
    const float* __restrict__ W1, const float* __restrict__ b1,
    const float* __restrict__ W2)
{
    int blk = blockIdx.x;

    if (blk >= NPRE) {
        int idx = (blk - NPRE) * 256 + threadIdx.x;
        int total = DFF * 128 + DOUT * DFF;
        for (; idx < total; idx += NPREP * 256) {
            if (idx < DFF * 128) {
                int n = idx >> 7, k = idx & 127;
                g_W1T[n * LDA + k] = __float2half(W1[(128 + k) * DFF + n]);
            } else {
                int j = idx - DFF * 128;
                int n = j >> 8, k = j & 255;
                g_W2T[n * 264 + k] = __float2half(W2[k * DOUT + n]);
            }
        }
        return;
    }

    bool isQ = blk < BB * NQ;
    int bn = isQ ? blk : blk - BB * NQ;

    const float* inv  = isQ ? (q_inv + bn * DINV) : (k_inv + bn * DINV);
    const float* W    = isQ ? Wq : Wk;
    const float* bias = isQ ? bq : bk;
    const float* W1s  = isQ ? W1 : (W1 + DMSG * DFF);
    __half* A         = isQ ? (g_Aqh + bn * DFF) : (g_Akh + bn * DFF);

    __shared__ float s_inv[DINV];
    __shared__ float s_part[4][DMSG];
    __shared__ float s_msg[DMSG];

    int tid = threadIdx.x;
    s_inv[tid] = inv[tid];
    __syncthreads();

    int m = tid & 63, g = tid >> 6;
    float acc = 0.f;
    #pragma unroll 16
    for (int i = g * 64; i < g * 64 + 64; i++)
        acc = fmaf(s_inv[i], W[i * DMSG + m], acc);
    s_part[g][m] = acc;
    __syncthreads();
    if (tid < DMSG)
        s_msg[tid] = s_part[0][tid] + s_part[1][tid] + s_part[2][tid] + s_part[3][tid] + bias[tid];
    __syncthreads();

    float a = isQ ? b1[tid] : 0.f;
    #pragma unroll 32
    for (int mm = 0; mm < DMSG; mm++)
        a = fmaf(s_msg[mm], W1s[mm * DFF + tid], a);
    A[tid] = __float2half(a);
}

// ---------------- W chunk prefetch via cp.async ----------------
__device__ __forceinline__ void prefetch_w(int c, uint32_t w1dst, uint32_t w2dst, int tid) {
    const char* src1 = (const char*)(g_W1T + c * 64 * LDA);
    #pragma unroll
    for (int i = tid; i < 1088; i += 256)
        CP_ASYNC16(w1dst + i * 16, src1 + i * 16);
    #pragma unroll
    for (int i = tid; i < 512; i += 256) {
        int row = i >> 3, seg = i & 7;
        CP_ASYNC16(w2dst + (row * LDH + seg * 8) * 2,
                   (const char*)(g_W2T + row * 264 + c * 64 + seg * 8));
    }
}

// ---------------- main pairwise kernel (2 CTAs/SM) ----------------
__global__ void __launch_bounds__(256, 2) pair_kernel(
    const float* __restrict__ q_equi, const float* __restrict__ k_equi,
    const float* __restrict__ b2, float* __restrict__ out)
{
    extern __shared__ char smem[];
    const uint32_t sb = smem_u32(smem);
    int tid = threadIdx.x;
    int w = tid >> 5, lane = tid & 31;

    int b  = blockIdx.z;
    int q0 = blockIdx.y * TQ;
    int k0 = blockIdx.x * TK;

    const __half* sAqh = (const __half*)(smem + OFF_AQH);
    const __half* sAkh = (const __half*)(smem + OFF_AKH);
    const float*  sb2  = (const float*)(smem + OFF_B2);

    // ---- phase 0: async-stage equi (f32), Aq/Ak (f16), b2; prefetch W chunk0 ----
    {
        const char* qsrc = (const char*)(q_equi + (size_t)(b * NQ + q0) * 192);
        const char* ksrc = (const char*)(k_equi + (size_t)(b * NK + k0) * 192);
        #pragma unroll
        for (int i = tid; i < 768; i += 256)
            CP_ASYNC16(sb + OFF_QE + i * 16, qsrc + i * 16);
        for (int i = tid; i < 384; i += 256) {
            int row = i / 48, seg = i - row * 48;
            CP_ASYNC16(sb + OFF_KE + row * (LDKE * 4) + seg * 16,
                       ksrc + (row * 192 + seg * 4) * 4);
        }
        const char* aqsrc = (const char*)(g_Aqh + (size_t)(b * NQ + q0) * DFF);
        const char* aksrc = (const char*)(g_Akh + (size_t)(b * NK + k0) * DFF);
        #pragma unroll
        for (int i = tid; i < 512; i += 256) {
            int row = i >> 5, seg = i & 31;
            CP_ASYNC16(sb + OFF_AQH + row * (LDAQH * 2) + seg * 16, aqsrc + i * 16);
        }
        if (tid < 256) {
            int row = tid >> 5, seg = tid & 31;
            CP_ASYNC16(sb + OFF_AKH + row * (LDAQH * 2) + seg * 16, aksrc + tid * 16);
        }
        if (tid < 16) CP_ASYNC16(sb + OFF_B2 + tid * 16, (const char*)b2 + tid * 16);
        CP_COMMIT();                                       // G0: inputs
        prefetch_w(0, sb + OFF_W1C0, sb + OFF_W2C0, tid);
        CP_COMMIT();                                       // G1: W chunk 0
        CP_WAIT(1);                                        // inputs landed
        __syncthreads();
    }

    // ---- lane geometry ----
    const int r = lane >> 2, cp = (lane & 3) * 2;
    const int qi0 = 2 * w;               // pair row m_lo = 16w + r -> (q=2w, k=r); m_hi -> (2w+1, r)

    // ---- P2: dot & dist -> GEMM1 A-fragments directly in registers (f32x2 packed) ----
    uint32_t af[8][4];
    {
        const float* q0p = (const float*)(smem + OFF_QE) + qi0 * 192;
        const float* q1p = q0p + 192;
        const float* kp  = (const float*)(smem + OFF_KE) + r * LDKE;
        #pragma unroll
        for (int ww = 0; ww < 4; ww++) {
            #pragma unroll
            for (int hh = 0; hh < 2; hh++) {
                int e0 = ww * 16 + hh * 8 + cp;
                uint64_t k0v = pk2(*(const float2*)(kp + e0));
                uint64_t k1v = pk2(*(const float2*)(kp + e0 + 64));
                uint64_t k2v = pk2(*(const float2*)(kp + e0 + 128));
                uint64_t k0n = k0v ^ NEGMASK2;
                uint64_t k1n = k1v ^ NEGMASK2;
                uint64_t k2n = k2v ^ NEGMASK2;
                {   // row m_lo (q-row qi0)
                    uint64_t a0 = pk2(*(const float2*)(q0p + e0));
                    uint64_t a1 = pk2(*(const float2*)(q0p + e0 + 64));
                    uint64_t a2 = pk2(*(const float2*)(q0p + e0 + 128));
                    uint64_t d  = fma2_(a2, k2v, fma2_(a1, k1v, mul2_(a0, k0v)));
                    uint64_t f0 = add2_(a0, k0n);
                    uint64_t f1 = add2_(a1, k1n);
                    uint64_t f2 = add2_(a2, k2n);
                    uint64_t s  = fma2_(f2, f2, fma2_(f1, f1, mul2_(f0, f0)));
                    float2 df = upk2(d), sf = upk2(s);
                    __half2 hd = __floats2half2_rn(df.x, df.y);
                    __half2 hs = __floats2half2_rn(sqrt_ap(sf.x), sqrt_ap(sf.y));
                    af[ww][hh * 2 + 0]     = *(uint32_t*)&hd;
                    af[ww + 4][hh * 2 + 0] = *(uint32_t*)&hs;
                }
                {   // row m_hi (q-row qi0+1)
                    uint64_t a0 = pk2(*(const float2*)(q1p + e0));
                    uint64_t a1 = pk2(*(const float2*)(q1p + e0 + 64));
                    uint64_t a2 = pk2(*(const float2*)(q1p + e0 + 128));
                    uint64_t d  = fma2_(a2, k2v, fma2_(a1, k1v, mul2_(a0, k0v)));
                    uint64_t f0 = add2_(a0, k0n);
                    uint64_t f1 = add2_(a1, k1n);
                    uint64_t f2 = add2_(a2, k2n);
                    uint64_t s  = fma2_(f2, f2, fma2_(f1, f1, mul2_(f0, f0)));
                    float2 df = upk2(d), sf = upk2(s);
                    __half2 hd = __floats2half2_rn(df.x, df.y);
                    __half2 hs = __floats2half2_rn(sqrt_ap(sf.x), sqrt_ap(sf.y));
                    af[ww][hh * 2 + 1]     = *(uint32_t*)&hd;
                    af[ww + 4][hh * 2 + 1] = *(uint32_t*)&hs;
                }
            }
        }
    }

    // B-side ldmatrix bases (per W buffer)
    const int bRow = (lane & 7) + ((lane >> 4) << 3);
    const uint32_t bOff1 = (bRow * LDA + ((lane >> 3) & 1) * 8) * 2;
    const uint32_t bOff2 = (bRow * LDH + ((lane >> 3) & 1) * 8) * 2;
    const uint32_t b1Base[2] = { sb + OFF_W1C0 + bOff1, sb + OFF_W1C1 + bOff1 };
    const uint32_t b2Base[2] = { sb + OFF_W2C0 + bOff2, sb + OFF_W2C1 + bOff2 };
    const uint32_t w1Dst[2]  = { sb + OFF_W1C0, sb + OFF_W1C1 };
    const uint32_t w2Dst[2]  = { sb + OFF_W2C0, sb + OFF_W2C1 };

    float acc2[8][4];
    #pragma unroll
    for (int j = 0; j < 8; j++)
        #pragma unroll
        for (int i = 0; i < 4; i++) acc2[j][i] = 0.f;

    // ================= chunk loop over N (4 x 64), W double-buffered =================
    for (int c = 0; c < 4; c++) {
        CP_WAIT(0);            // W chunk c resident
        __syncthreads();       // visible to all; other buffer free for reuse

        if (c < 3) {           // prefetch chunk c+1
            prefetch_w(c + 1, w1Dst[(c + 1) & 1], w2Dst[(c + 1) & 1], tid);
            CP_COMMIT();
        }

        const uint32_t bA1 = b1Base[c & 1];
        const uint32_t bA2 = b2Base[c & 1];

        // ---- GEMM1 chunk: acc1[16,64] = A[16,128] @ W1c^T ----
        float acc1[8][4];
        #pragma unroll
        for (int j = 0; j < 8; j++)
            #pragma unroll
            for (int i = 0; i < 4; i++) acc1[j][i] = 0.f;

        #pragma unroll
        for (int kk = 0; kk < 8; kk++) {
            #pragma unroll
            for (int jp = 0; jp < 4; jp++) {
                uint32_t b0, b1r, b2r, b3;
                ldsm4(b0, b1r, b2r, b3, bA1 + jp * 16 * LDA * 2 + kk * 32);
                mma16816(acc1[2 * jp],     af[kk][0], af[kk][1], af[kk][2], af[kk][3], b0,  b1r);
                mma16816(acc1[2 * jp + 1], af[kk][0], af[kk][1], af[kk][2], af[kk][3], b2r, b3);
            }
        }

        // ---- epilogue1: + Aq + Ak (fp16, ak shared lo/hi), SiLU -> register h frags ----
        uint32_t hlo[8], hhi[8];
        {
            const __half* aqlo = sAqh + qi0 * LDAQH + c * 64;
            const __half* aqhi = aqlo + LDAQH;
            const __half* akr  = sAkh + r * LDAQH + c * 64;
            #pragma unroll
            for (int j = 0; j < 8; j++) {
                int n = j * 8 + cp;
                float2 aql = __half22float2(*(const __half2*)(aqlo + n));
                float2 aqh = __half22float2(*(const __half2*)(aqhi + n));
                float2 akl = __half22float2(*(const __half2*)(akr + n));
                float v0 = acc1[j][0] + aql.x + akl.x;
                float v1 = acc1[j][1] + aql.y + akl.y;
                float v2 = acc1[j][2] + aqh.x + akl.x;
                float v3 = acc1[j][3] + aqh.y + akl.y;
                __half2 x0 = __floats2half2_rn(v0, v1);
                __half2 x1 = __floats2half2_rn(v2, v3);
                hlo[j] = silu_h2(*(uint32_t*)&x0);
                hhi[j] = silu_h2(*(uint32_t*)&x1);
            }
        }

        // ---- GEMM2 partial: acc2 += h[16,64] @ W2c^T (h in registers) ----
        #pragma unroll
        for (int kk = 0; kk < 4; kk++) {
            uint32_t a0 = hlo[2 * kk], a1 = hhi[2 * kk];
            uint32_t a2 = hlo[2 * kk + 1], a3 = hhi[2 * kk + 1];
            #pragma unroll
            for (int jp = 0; jp < 4; jp++) {
                uint32_t b0, b1r, b2r, b3;
                ldsm4(b0, b1r, b2r, b3, bA2 + jp * 16 * LDH * 2 + kk * 32);
                mma16816(acc2[2 * jp],     a0, a1, a2, a3, b0,  b1r);
                mma16816(acc2[2 * jp + 1], a0, a1, a2, a3, b2r, b3);
            }
        }
    }

    // ---- epilogue2: + b2, store ----
    {
        float* olo = out + ((size_t)(b * NQ + q0 + qi0) * NK + (k0 + r)) * DOUT;
        float* ohi = olo + (size_t)NK * DOUT;
        #pragma unroll
        for (int j = 0; j < 8; j++) {
            int n = j * 8 + cp;
            float2 v0, v1;
            v0.x = acc2[j][0] + sb2[n];
            v0.y = acc2[j][1] + sb2[n + 1];
            v1.x = acc2[j][2] + sb2[n];
            v1.y = acc2[j][3] + sb2[n + 1];
            *(float2*)(olo + n) = v0;
            *(float2*)(ohi + n) = v1;
        }
    }
}

// ---------------------------------------------------------------------------
extern "C" void kernel_launch(void* const* d_in, const int* in_sizes, int n_in,
                              void* d_out, int out_size)
{
    const float* q_equi = (const float*)d_in[0];
    const float* q_inv  = (const float*)d_in[1];
    const float* k_equi = (const float*)d_in[2];
    const float* k_inv  = (const float*)d_in[3];
    const float* Wq     = (const float*)d_in[4];
    const float* bq     = (const float*)d_in[5];
    const float* Wk     = (const float*)d_in[6];
    const float* bk     = (const float*)d_in[7];
    const float* W1     = (const float*)d_in[8];
    const float* b1     = (const float*)d_in[9];
    const float* W2     = (const float*)d_in[10];
    const float* b2     = (const float*)d_in[11];
    float* out = (float*)d_out;

    cudaFuncSetAttribute(pair_kernel, cudaFuncAttributeMaxDynamicSharedMemorySize, SMEM_BYTES);

    prelude_kernel<<<NPRE + NPREP, 256>>>(q_inv, k_inv, Wq, bq, Wk, bk, W1, b1, W2);

    dim3 grid(NK / TK, NQ / TQ, BB);
    pair_kernel<<<grid, 256, SMEM_BYTES>>>(q_equi, k_equi, b2, out);
}

// round 14
// speedup vs baseline: 1.1973x; 1.0643x over previous
#include <cuda_runtime.h>
#include <cuda_fp16.h>
#include <cstdint>

// ---------------- problem constants ----------------
#define BB    4
#define NQ    384
#define NK    384
#define DE    64
#define DMSG  64
#define DFF   256
#define DOUT  64
#define DINV  256

#define TQ    16
#define TK    8
#define TM    128

#define LDA   136          // half pitch for W1 chunk tiles (k=128 + 8 pad)
#define LDH   72           // half pitch for W2 chunk tiles (k=64 + 8 pad)
#define LDKE  212          // float pitch for k-equi staging (bank-spread)
#define LDAQH 264          // half pitch for sAqh/sAkh

#define PRE_ROWS 16
#define NPRE2 (BB * (NQ + NK) / PRE_ROWS)   // 192 blocks (96 q + 96 k)
#define NPREP 96                            // weight-prep blocks appended

// ---------------- device scratch ----------------
__device__ __half g_Aqh[BB * NQ * DFF];
__device__ __half g_Akh[BB * NK * DFF];
__device__ __align__(16) __half g_W1T[DFF * LDA];   // [n=256][pitch 136]
__device__ __align__(16) __half g_W2T[DOUT * 264];  // [n=64][pitch 264]

// ---------------- SMEM map (bytes) — pair kernel ----------------
#define OFF_QE    0        // 16*192*4 = 12288
#define OFF_KE    12288    //  8*212*4 =  6784
#define OFF_AQH   19072    // 16*264*2 =  8448
#define OFF_AKH   27520    //  8*264*2 =  4224
#define OFF_W1C0  31744    // 17408
#define OFF_W1C1  49152    // 17408
#define OFF_W2C0  66560    //  9216
#define OFF_W2C1  75776    //  9216
#define OFF_B2    84992    //   256
#define SMEM_BYTES 85248

__device__ __forceinline__ uint32_t smem_u32(const void* p) {
    uint32_t a;
    asm("{ .reg .u64 t; cvta.to.shared.u64 t, %1; cvt.u32.u64 %0, t; }" : "=r"(a) : "l"(p));
    return a;
}
#define CP_ASYNC16(dst, src) \
    asm volatile("cp.async.cg.shared.global [%0], [%1], 16;" :: "r"(dst), "l"(src))
#define CP_COMMIT() asm volatile("cp.async.commit_group;" ::: "memory")
#define CP_WAIT(n)  asm volatile("cp.async.wait_group %0;" :: "n"(n) : "memory")

__device__ __forceinline__ void ldsm4(uint32_t& r0, uint32_t& r1, uint32_t& r2, uint32_t& r3,
                                      uint32_t addr) {
    asm volatile("ldmatrix.sync.aligned.m8n8.x4.shared.b16 {%0,%1,%2,%3}, [%4];"
        : "=r"(r0), "=r"(r1), "=r"(r2), "=r"(r3) : "r"(addr));
}
__device__ __forceinline__ void mma16816(float* c, uint32_t a0, uint32_t a1, uint32_t a2,
                                         uint32_t a3, uint32_t b0, uint32_t b1) {
    asm volatile(
        "mma.sync.aligned.m16n8k16.row.col.f32.f16.f16.f32 "
        "{%0,%1,%2,%3}, {%4,%5,%6,%7}, {%8,%9}, {%0,%1,%2,%3};"
        : "+f"(c[0]), "+f"(c[1]), "+f"(c[2]), "+f"(c[3])
        : "r"(a0), "r"(a1), "r"(a2), "r"(a3), "r"(b0), "r"(b1));
}
__device__ __forceinline__ uint32_t silu_h2(uint32_t xu) {
    uint32_t hxu, tu, res;
    asm("mul.rn.f16x2 %0, %1, %2;" : "=r"(hxu) : "r"(xu), "r"(0x38003800u));
    asm("tanh.approx.f16x2 %0, %1;" : "=r"(tu) : "r"(hxu));
    asm("fma.rn.f16x2 %0, %1, %2, %3;" : "=r"(res) : "r"(hxu), "r"(tu), "r"(hxu));
    return res;
}

// ---------------- packed f32x2 helpers ----------------
__device__ __forceinline__ uint64_t pk2(float2 v) {
    uint64_t r; asm("mov.b64 %0, {%1, %2};" : "=l"(r) : "f"(v.x), "f"(v.y)); return r;
}
__device__ __forceinline__ float2 upk2(uint64_t v) {
    float2 r; asm("mov.b64 {%0, %1}, %2;" : "=f"(r.x), "=f"(r.y) : "l"(v)); return r;
}
__device__ __forceinline__ uint64_t mul2_(uint64_t a, uint64_t b) {
    uint64_t d; asm("mul.rn.f32x2 %0, %1, %2;" : "=l"(d) : "l"(a), "l"(b)); return d;
}
__device__ __forceinline__ uint64_t add2_(uint64_t a, uint64_t b) {
    uint64_t d; asm("add.rn.f32x2 %0, %1, %2;" : "=l"(d) : "l"(a), "l"(b)); return d;
}
__device__ __forceinline__ uint64_t fma2_(uint64_t a, uint64_t b, uint64_t c) {
    uint64_t d; asm("fma.rn.f32x2 %0, %1, %2, %3;" : "=l"(d) : "l"(a), "l"(b), "l"(c)); return d;
}
__device__ __forceinline__ float sqrt_ap(float x) {
    float r; asm("sqrt.approx.f32 %0, %1;" : "=f"(r) : "f"(x)); return r;
}
#define NEGMASK2 0x8000000080000000ULL

// ---------------- prelude v2: 16 rows/block, weights read once per block ----------------
__global__ void __launch_bounds__(256) prelude_kernel(
    const float* __restrict__ q_inv, const float* __restrict__ k_inv,
    const float* __restrict__ Wq, const float* __restrict__ bq,
    const float* __restrict__ Wk, const float* __restrict__ bk,
    const float* __restrict__ W1, const float* __restrict__ b1,
    const float* __restrict__ W2)
{
    int blk = blockIdx.x;

    if (blk >= NPRE2) {
        // weight prep: transpose + fp16 (49152 elements, 96 blocks x 256 thr x 2 iters)
        int idx = (blk - NPRE2) * 256 + threadIdx.x;
        int total = DFF * 128 + DOUT * DFF;
        for (; idx < total; idx += NPREP * 256) {
            if (idx < DFF * 128) {
                int n = idx >> 7, k = idx & 127;
                g_W1T[n * LDA + k] = __float2half(W1[(128 + k) * DFF + n]);
            } else {
                int j = idx - DFF * 128;
                int n = j >> 8, k = j & 255;
                g_W2T[n * 264 + k] = __float2half(W2[k * DOUT + n]);
            }
        }
        return;
    }

    bool isQ = blk < (BB * NQ / PRE_ROWS);          // blk < 96
    int rowbase = (isQ ? blk : blk - BB * NQ / PRE_ROWS) * PRE_ROWS;

    const float* inv  = (isQ ? q_inv : k_inv) + (size_t)rowbase * DINV;
    const float* W    = isQ ? Wq : Wk;
    const float* bias = isQ ? bq : bk;
    const float* W1s  = isQ ? W1 : (W1 + DMSG * DFF);
    __half* A         = (isQ ? g_Aqh : g_Akh) + (size_t)rowbase * DFF;

    __shared__ float s_inv[16 * 260];     // pitch 260 (≡4 mod 32 banks)
    __shared__ float s_part[4 * 16 * 64];
    __shared__ float s_msg[16 * 68];      // pitch 68

    int tid = threadIdx.x;

    // stage inv [16,256]
    for (int idx = tid; idx < 1024; idx += 256) {
        int row = idx >> 6, seg = idx & 63;
        *(float4*)&s_inv[row * 260 + seg * 4] = *(const float4*)(inv + row * 256 + seg * 4);
    }
    __syncthreads();

    // phase A: msg[16,64] = inv @ W  (thread: m = tid&63, i-range by g = tid>>6)
    {
        int m = tid & 63, g = tid >> 6;
        float acc[16];
        #pragma unroll
        for (int row = 0; row < 16; row++) acc[row] = 0.f;
        for (int i = g * 64; i < g * 64 + 64; i += 4) {
            float w0 = W[(i + 0) * DMSG + m];
            float w1 = W[(i + 1) * DMSG + m];
            float w2 = W[(i + 2) * DMSG + m];
            float w3 = W[(i + 3) * DMSG + m];
            #pragma unroll
            for (int row = 0; row < 16; row++) {
                float4 v = *(const float4*)&s_inv[row * 260 + i];
                acc[row] = fmaf(v.w, w3, fmaf(v.z, w2, fmaf(v.y, w1, fmaf(v.x, w0, acc[row]))));
            }
        }
        #pragma unroll
        for (int row = 0; row < 16; row++) s_part[(g * 16 + row) * 64 + m] = acc[row];
    }
    __syncthreads();
    for (int v = tid; v < 1024; v += 256) {
        int row = v >> 6, mm = v & 63;
        s_msg[row * 68 + mm] = s_part[row * 64 + mm] + s_part[(16 + row) * 64 + mm]
                             + s_part[(32 + row) * 64 + mm] + s_part[(48 + row) * 64 + mm]
                             + bias[mm];
    }
    __syncthreads();

    // phase B: A[16,256] = msg @ W1s (+b1 for q); thread owns column ff = tid
    {
        int ff = tid;
        float binit = isQ ? b1[ff] : 0.f;
        float acc[16];
        #pragma unroll
        for (int row = 0; row < 16; row++) acc[row] = binit;
        for (int mm = 0; mm < 64; mm += 4) {
            float w0 = W1s[(mm + 0) * DFF + ff];
            float w1 = W1s[(mm + 1) * DFF + ff];
            float w2 = W1s[(mm + 2) * DFF + ff];
            float w3 = W1s[(mm + 3) * DFF + ff];
            #pragma unroll
            for (int row = 0; row < 16; row++) {
                float4 mv = *(const float4*)&s_msg[row * 68 + mm];
                acc[row] = fmaf(mv.w, w3, fmaf(mv.z, w2, fmaf(mv.y, w1, fmaf(mv.x, w0, acc[row]))));
            }
        }
        #pragma unroll
        for (int row = 0; row < 16; row++)
            A[row * DFF + ff] = __float2half(acc[row]);
    }
}

// ---------------- W chunk prefetch via cp.async ----------------
__device__ __forceinline__ void prefetch_w(int c, uint32_t w1dst, uint32_t w2dst, int tid) {
    const char* src1 = (const char*)(g_W1T + c * 64 * LDA);
    #pragma unroll
    for (int i = tid; i < 1088; i += 256)
        CP_ASYNC16(w1dst + i * 16, src1 + i * 16);
    #pragma unroll
    for (int i = tid; i < 512; i += 256) {
        int row = i >> 3, seg = i & 7;
        CP_ASYNC16(w2dst + (row * LDH + seg * 8) * 2,
                   (const char*)(g_W2T + row * 264 + c * 64 + seg * 8));
    }
}

// ---------------- main pairwise kernel (2 CTAs/SM) ----------------
__global__ void __launch_bounds__(256, 2) pair_kernel(
    const float* __restrict__ q_equi, const float* __restrict__ k_equi,
    const float* __restrict__ b2, float* __restrict__ out)
{
    extern __shared__ char smem[];
    const uint32_t sb = smem_u32(smem);
    int tid = threadIdx.x;
    int w = tid >> 5, lane = tid & 31;

    int b  = blockIdx.z;
    int q0 = blockIdx.y * TQ;
    int k0 = blockIdx.x * TK;

    const __half* sAqh = (const __half*)(smem + OFF_AQH);
    const __half* sAkh = (const __half*)(smem + OFF_AKH);
    const float*  sb2  = (const float*)(smem + OFF_B2);

    // ---- phase 0: async-stage equi (f32), Aq/Ak (f16), b2; prefetch W chunk0 ----
    {
        const char* qsrc = (const char*)(q_equi + (size_t)(b * NQ + q0) * 192);
        const char* ksrc = (const char*)(k_equi + (size_t)(b * NK + k0) * 192);
        #pragma unroll
        for (int i = tid; i < 768; i += 256)
            CP_ASYNC16(sb + OFF_QE + i * 16, qsrc + i * 16);
        for (int i = tid; i < 384; i += 256) {
            int row = i / 48, seg = i - row * 48;
            CP_ASYNC16(sb + OFF_KE + row * (LDKE * 4) + seg * 16,
                       ksrc + (row * 192 + seg * 4) * 4);
        }
        const char* aqsrc = (const char*)(g_Aqh + (size_t)(b * NQ + q0) * DFF);
        const char* aksrc = (const char*)(g_Akh + (size_t)(b * NK + k0) * DFF);
        #pragma unroll
        for (int i = tid; i < 512; i += 256) {
            int row = i >> 5, seg = i & 31;
            CP_ASYNC16(sb + OFF_AQH + row * (LDAQH * 2) + seg * 16, aqsrc + i * 16);
        }
        if (tid < 256) {
            int row = tid >> 5, seg = tid & 31;
            CP_ASYNC16(sb + OFF_AKH + row * (LDAQH * 2) + seg * 16, aksrc + tid * 16);
        }
        if (tid < 16) CP_ASYNC16(sb + OFF_B2 + tid * 16, (const char*)b2 + tid * 16);
        CP_COMMIT();                                       // G0: inputs
        prefetch_w(0, sb + OFF_W1C0, sb + OFF_W2C0, tid);
        CP_COMMIT();                                       // G1: W chunk 0
        CP_WAIT(1);                                        // inputs landed
        __syncthreads();
    }

    // ---- lane geometry ----
    const int r = lane >> 2, cp = (lane & 3) * 2;
    const int qi0 = 2 * w;               // pair row m_lo = 16w + r -> (q=2w, k=r); m_hi -> (2w+1, r)

    // ---- P2: dot & dist -> GEMM1 A-fragments directly in registers (f32x2 packed) ----
    uint32_t af[8][4];
    {
        const float* q0p = (const float*)(smem + OFF_QE) + qi0 * 192;
        const float* q1p = q0p + 192;
        const float* kp  = (const float*)(smem + OFF_KE) + r * LDKE;
        #pragma unroll
        for (int ww = 0; ww < 4; ww++) {
            #pragma unroll
            for (int hh = 0; hh < 2; hh++) {
                int e0 = ww * 16 + hh * 8 + cp;
                uint64_t k0v = pk2(*(const float2*)(kp + e0));
                uint64_t k1v = pk2(*(const float2*)(kp + e0 + 64));
                uint64_t k2v = pk2(*(const float2*)(kp + e0 + 128));
                uint64_t k0n = k0v ^ NEGMASK2;
                uint64_t k1n = k1v ^ NEGMASK2;
                uint64_t k2n = k2v ^ NEGMASK2;
                {   // row m_lo (q-row qi0)
                    uint64_t a0 = pk2(*(const float2*)(q0p + e0));
                    uint64_t a1 = pk2(*(const float2*)(q0p + e0 + 64));
                    uint64_t a2 = pk2(*(const float2*)(q0p + e0 + 128));
                    uint64_t d  = fma2_(a2, k2v, fma2_(a1, k1v, mul2_(a0, k0v)));
                    uint64_t f0 = add2_(a0, k0n);
                    uint64_t f1 = add2_(a1, k1n);
                    uint64_t f2 = add2_(a2, k2n);
                    uint64_t s  = fma2_(f2, f2, fma2_(f1, f1, mul2_(f0, f0)));
                    float2 df = upk2(d), sf = upk2(s);
                    __half2 hd = __floats2half2_rn(df.x, df.y);
                    __half2 hs = __floats2half2_rn(sqrt_ap(sf.x), sqrt_ap(sf.y));
                    af[ww][hh * 2 + 0]     = *(uint32_t*)&hd;
                    af[ww + 4][hh * 2 + 0] = *(uint32_t*)&hs;
                }
                {   // row m_hi (q-row qi0+1)
                    uint64_t a0 = pk2(*(const float2*)(q1p + e0));
                    uint64_t a1 = pk2(*(const float2*)(q1p + e0 + 64));
                    uint64_t a2 = pk2(*(const float2*)(q1p + e0 + 128));
                    uint64_t d  = fma2_(a2, k2v, fma2_(a1, k1v, mul2_(a0, k0v)));
                    uint64_t f0 = add2_(a0, k0n);
                    uint64_t f1 = add2_(a1, k1n);
                    uint64_t f2 = add2_(a2, k2n);
                    uint64_t s  = fma2_(f2, f2, fma2_(f1, f1, mul2_(f0, f0)));
                    float2 df = upk2(d), sf = upk2(s);
                    __half2 hd = __floats2half2_rn(df.x, df.y);
                    __half2 hs = __floats2half2_rn(sqrt_ap(sf.x), sqrt_ap(sf.y));
                    af[ww][hh * 2 + 1]     = *(uint32_t*)&hd;
                    af[ww + 4][hh * 2 + 1] = *(uint32_t*)&hs;
                }
            }
        }
    }

    // B-side ldmatrix bases (per W buffer)
    const int bRow = (lane & 7) + ((lane >> 4) << 3);
    const uint32_t bOff1 = (bRow * LDA + ((lane >> 3) & 1) * 8) * 2;
    const uint32_t bOff2 = (bRow * LDH + ((lane >> 3) & 1) * 8) * 2;
    const uint32_t b1Base[2] = { sb + OFF_W1C0 + bOff1, sb + OFF_W1C1 + bOff1 };
    const uint32_t b2Base[2] = { sb + OFF_W2C0 + bOff2, sb + OFF_W2C1 + bOff2 };
    const uint32_t w1Dst[2]  = { sb + OFF_W1C0, sb + OFF_W1C1 };
    const uint32_t w2Dst[2]  = { sb + OFF_W2C0, sb + OFF_W2C1 };

    float acc2[8][4];
    #pragma unroll
    for (int j = 0; j < 8; j++)
        #pragma unroll
        for (int i = 0; i < 4; i++) acc2[j][i] = 0.f;

    // ================= chunk loop over N (4 x 64), W double-buffered =================
    for (int c = 0; c < 4; c++) {
        CP_WAIT(0);            // W chunk c resident
        __syncthreads();       // visible to all; other buffer free for reuse

        if (c < 3) {           // prefetch chunk c+1
            prefetch_w(c + 1, w1Dst[(c + 1) & 1], w2Dst[(c + 1) & 1], tid);
            CP_COMMIT();
        }

        const uint32_t bA1 = b1Base[c & 1];
        const uint32_t bA2 = b2Base[c & 1];

        // ---- init acc1 with Aq + Ak (folded into MMA C-operand) ----
        float acc1[8][4];
        {
            const __half* aqlo = sAqh + qi0 * LDAQH + c * 64;
            const __half* aqhi = aqlo + LDAQH;
            const __half* akr  = sAkh + r * LDAQH + c * 64;
            #pragma unroll
            for (int j = 0; j < 8; j++) {
                int n = j * 8 + cp;
                float2 aql = __half22float2(*(const __half2*)(aqlo + n));
                float2 aqh = __half22float2(*(const __half2*)(aqhi + n));
                float2 akl = __half22float2(*(const __half2*)(akr + n));
                acc1[j][0] = aql.x + akl.x;
                acc1[j][1] = aql.y + akl.y;
                acc1[j][2] = aqh.x + akl.x;
                acc1[j][3] = aqh.y + akl.y;
            }
        }

        // ---- GEMM1 chunk: acc1 += A[16,128] @ W1c^T ----
        #pragma unroll
        for (int kk = 0; kk < 8; kk++) {
            #pragma unroll
            for (int jp = 0; jp < 4; jp++) {
                uint32_t b0, b1r, b2r, b3;
                ldsm4(b0, b1r, b2r, b3, bA1 + jp * 16 * LDA * 2 + kk * 32);
                mma16816(acc1[2 * jp],     af[kk][0], af[kk][1], af[kk][2], af[kk][3], b0,  b1r);
                mma16816(acc1[2 * jp + 1], af[kk][0], af[kk][1], af[kk][2], af[kk][3], b2r, b3);
            }
        }

        // ---- epilogue1: cvt + SiLU only -> register h fragments ----
        uint32_t hlo[8], hhi[8];
        #pragma unroll
        for (int j = 0; j < 8; j++) {
            __half2 x0 = __floats2half2_rn(acc1[j][0], acc1[j][1]);
            __half2 x1 = __floats2half2_rn(acc1[j][2], acc1[j][3]);
            hlo[j] = silu_h2(*(uint32_t*)&x0);
            hhi[j] = silu_h2(*(uint32_t*)&x1);
        }

        // ---- GEMM2 partial: acc2 += h[16,64] @ W2c^T (h in registers) ----
        #pragma unroll
        for (int kk = 0; kk < 4; kk++) {
            uint32_t a0 = hlo[2 * kk], a1 = hhi[2 * kk];
            uint32_t a2 = hlo[2 * kk + 1], a3 = hhi[2 * kk + 1];
            #pragma unroll
            for (int jp = 0; jp < 4; jp++) {
                uint32_t b0, b1r, b2r, b3;
                ldsm4(b0, b1r, b2r, b3, bA2 + jp * 16 * LDH * 2 + kk * 32);
                mma16816(acc2[2 * jp],     a0, a1, a2, a3, b0,  b1r);
                mma16816(acc2[2 * jp + 1], a0, a1, a2, a3, b2r, b3);
            }
        }
    }

    // ---- epilogue2: + b2, store ----
    {
        float* olo = out + ((size_t)(b * NQ + q0 + qi0) * NK + (k0 + r)) * DOUT;
        float* ohi = olo + (size_t)NK * DOUT;
        #pragma unroll
        for (int j = 0; j < 8; j++) {
            int n = j * 8 + cp;
            float2 v0, v1;
            v0.x = acc2[j][0] + sb2[n];
            v0.y = acc2[j][1] + sb2[n + 1];
            v1.x = acc2[j][2] + sb2[n];
            v1.y = acc2[j][3] + sb2[n + 1];
            *(float2*)(olo + n) = v0;
            *(float2*)(ohi + n) = v1;
        }
    }
}

// ---------------------------------------------------------------------------
extern "C" void kernel_launch(void* const* d_in, const int* in_sizes, int n_in,
                              void* d_out, int out_size)
{
    const float* q_equi = (const float*)d_in[0];
    const float* q_inv  = (const float*)d_in[1];
    const float* k_equi = (const float*)d_in[2];
    const float* k_inv  = (const float*)d_in[3];
    const float* Wq     = (const float*)d_in[4];
    const float* bq     = (const float*)d_in[5];
    const float* Wk     = (const float*)d_in[6];
    const float* bk     = (const float*)d_in[7];
    const float* W1     = (const float*)d_in[8];
    const float* b1     = (const float*)d_in[9];
    const float* W2     = (const float*)d_in[10];
    const float* b2     = (const float*)d_in[11];
    float* out = (float*)d_out;

    cudaFuncSetAttribute(pair_kernel, cudaFuncAttributeMaxDynamicSharedMemorySize, SMEM_BYTES);

    prelude_kernel<<<NPRE2 + NPREP, 256>>>(q_inv, k_inv, Wq, bq, Wk, bk, W1, b1, W2);

    dim3 grid(NK / TK, NQ / TQ, BB);
    pair_kernel<<<grid, 256, SMEM_BYTES>>>(q_equi, k_equi, b2, out);
}